// round 4
// baseline (speedup 1.0000x reference)
#include <cuda_runtime.h>

// Problem dims (fixed by the dataset)
#define NTOK 4096
#define HDIM 1024
#define FDIM 2048
#define EXPE 8
#define NPAIR (NTOK * 2)

// ---- scratch (static device globals; no runtime allocation) ----
__device__ float g_phi[(size_t)NPAIR * FDIM];   // 64 MB: silu(v)*u per (token,expert) pair
__device__ int   g_cnt[EXPE];
__device__ int   g_off[EXPE + 1];
__device__ int   g_cur[EXPE];
__device__ int   g_tok_e[NTOK * 2];
__device__ float g_tok_w[NTOK * 2];
__device__ int   g_row_tok[NPAIR];
__device__ float g_row_w[NPAIR];

// ---------------------------------------------------------------
// 0) init: zero the main output region and the per-expert counters
// ---------------------------------------------------------------
__global__ void init_kernel(float* __restrict__ out) {
    int tid = blockIdx.x * blockDim.x + threadIdx.x;
    if (tid < EXPE) g_cnt[tid] = 0;
    const int total = NTOK * HDIM;
    for (int i = tid * 4; i < total; i += gridDim.x * blockDim.x * 4) {
        float4 z = make_float4(0.f, 0.f, 0.f, 0.f);
        *reinterpret_cast<float4*>(out + i) = z;
    }
}

// ---------------------------------------------------------------
// 1) router: logits = x @ gate_w^T, softmax, top-2, combine weights
// ---------------------------------------------------------------
__global__ void router_kernel(const float* __restrict__ x,
                              const float* __restrict__ gw,
                              float* __restrict__ rl_out) {
    __shared__ float sgw[EXPE * HDIM];   // 32 KB
    int tid = threadIdx.x;               // 128
    for (int i = tid; i < EXPE * HDIM; i += 128) sgw[i] = gw[i];
    __syncthreads();

    int warp = tid >> 5, lane = tid & 31;
    int n = blockIdx.x * 4 + warp;
    if (n >= NTOK) return;
    const float* xr = x + (size_t)n * HDIM;

    float acc[EXPE];
#pragma unroll
    for (int e = 0; e < EXPE; e++) acc[e] = 0.f;

    for (int h = lane; h < HDIM; h += 32) {
        float xv = xr[h];
#pragma unroll
        for (int e = 0; e < EXPE; e++) acc[e] += xv * sgw[e * HDIM + h];
    }
#pragma unroll
    for (int e = 0; e < EXPE; e++) {
#pragma unroll
        for (int o = 16; o > 0; o >>= 1)
            acc[e] += __shfl_xor_sync(0xffffffffu, acc[e], o);
    }

    if (lane == 0) {
#pragma unroll
        for (int e = 0; e < EXPE; e++) rl_out[(size_t)n * EXPE + e] = acc[e];
        float m = acc[0];
#pragma unroll
        for (int e = 1; e < EXPE; e++) m = fmaxf(m, acc[e]);
        float p[EXPE];
#pragma unroll
        for (int e = 0; e < EXPE; e++) p[e] = __expf(acc[e] - m);
        int i0 = 0;
#pragma unroll
        for (int e = 1; e < EXPE; e++) if (p[e] > p[i0]) i0 = e;
        int i1 = (i0 == 0) ? 1 : 0;
#pragma unroll
        for (int e = 0; e < EXPE; e++)
            if (e != i0 && p[e] > p[i1]) i1 = e;
        float s2 = p[i0] + p[i1];
        float w0 = p[i0] / s2;
        float w1 = p[i1] / s2;
        g_tok_e[n * 2 + 0] = i0; g_tok_w[n * 2 + 0] = w0;
        g_tok_e[n * 2 + 1] = i1; g_tok_w[n * 2 + 1] = w1;
        atomicAdd(&g_cnt[i0], 1);
        atomicAdd(&g_cnt[i1], 1);
    }
}

// ---------------------------------------------------------------
// 2) exclusive scan over 8 counters
// ---------------------------------------------------------------
__global__ void scan_kernel() {
    if (threadIdx.x == 0 && blockIdx.x == 0) {
        int acc = 0;
        for (int e = 0; e < EXPE; e++) {
            g_off[e] = acc;
            g_cur[e] = acc;
            acc += g_cnt[e];
        }
        g_off[EXPE] = acc;
    }
}

// ---------------------------------------------------------------
// 3) scatter tokens into compacted per-expert row lists
// ---------------------------------------------------------------
__global__ void scatter_kernel() {
    int n = blockIdx.x * blockDim.x + threadIdx.x;
    if (n >= NTOK) return;
#pragma unroll
    for (int k = 0; k < 2; k++) {
        int e = g_tok_e[n * 2 + k];
        float w = g_tok_w[n * 2 + k];
        int pos = atomicAdd(&g_cur[e], 1);
        g_row_tok[pos] = n;
        g_row_w[pos] = w;
    }
}

// ---------------------------------------------------------------
// 4) up+gate GEMM -> phi = silu(v) * u
// ---------------------------------------------------------------
#define TM 64
#define TN 64
#define TK 16

__global__ __launch_bounds__(256) void up_gate_kernel(
    const float* __restrict__ x,
    const float* __restrict__ w_up, const float* __restrict__ w_gate,
    const float* __restrict__ b_up, const float* __restrict__ b_gate) {
    int e = blockIdx.y >> 6;
    int t = blockIdx.y & 63;
    int cnt = g_cnt[e];
    int m0 = t * TM;
    if (m0 >= cnt) return;
    int base = g_off[e] + m0;
    int valid = min(TM, cnt - m0);
    int f0 = blockIdx.x * TN;

    __shared__ float Xs[TM][TK + 1];
    __shared__ float Us[TK][TN + 4];
    __shared__ float Gs[TK][TN + 4];
    __shared__ int toks[TM];

    int tid = threadIdx.x;
    if (tid < TM) toks[tid] = g_row_tok[base + min(tid, valid - 1)];
    __syncthreads();

    const float* Wu = w_up + (size_t)e * HDIM * FDIM;
    const float* Wg = w_gate + (size_t)e * HDIM * FDIM;

    float accU[4][4], accG[4][4];
#pragma unroll
    for (int i = 0; i < 4; i++)
#pragma unroll
        for (int j = 0; j < 4; j++) { accU[i][j] = 0.f; accG[i][j] = 0.f; }

    int tx = tid & 15, ty = tid >> 4;

    for (int k0 = 0; k0 < HDIM; k0 += TK) {
#pragma unroll
        for (int i = 0; i < 4; i++) {
            int li = tid + 256 * i;
            int m = li >> 4, k = li & 15;
            Xs[m][k] = x[(size_t)toks[m] * HDIM + k0 + k];
        }
#pragma unroll
        for (int i = 0; i < 4; i++) {
            int li = tid + 256 * i;
            int k = li >> 6, f = li & 63;
            size_t off = (size_t)(k0 + k) * FDIM + f0 + f;
            Us[k][f] = Wu[off];
            Gs[k][f] = Wg[off];
        }
        __syncthreads();
#pragma unroll
        for (int kk = 0; kk < TK; kk++) {
            float a[4];
#pragma unroll
            for (int i = 0; i < 4; i++) a[i] = Xs[ty * 4 + i][kk];
            float4 bu = *reinterpret_cast<const float4*>(&Us[kk][tx * 4]);
            float4 bg = *reinterpret_cast<const float4*>(&Gs[kk][tx * 4]);
#pragma unroll
            for (int i = 0; i < 4; i++) {
                accU[i][0] += a[i] * bu.x; accU[i][1] += a[i] * bu.y;
                accU[i][2] += a[i] * bu.z; accU[i][3] += a[i] * bu.w;
                accG[i][0] += a[i] * bg.x; accG[i][1] += a[i] * bg.y;
                accG[i][2] += a[i] * bg.z; accG[i][3] += a[i] * bg.w;
            }
        }
        __syncthreads();
    }

#pragma unroll
    for (int i = 0; i < 4; i++) {
        int m = ty * 4 + i;
        if (m >= valid) continue;
        size_t rowoff = (size_t)(base + m) * FDIM + f0;
        float4 ph;
        float* php = reinterpret_cast<float*>(&ph);
#pragma unroll
        for (int j = 0; j < 4; j++) {
            int f = tx * 4 + j;
            float u = accU[i][j] + b_up[e * FDIM + f0 + f];
            float v = accG[i][j] + b_gate[e * FDIM + f0 + f];
            float sg = 1.f / (1.f + __expf(-v));
            php[j] = (v * sg) * u;
        }
        *reinterpret_cast<float4*>(&g_phi[rowoff + tx * 4]) = ph;
    }
}

// ---------------------------------------------------------------
// 5) down GEMM + weighted combine
// ---------------------------------------------------------------
__global__ __launch_bounds__(256) void down_kernel(
    const float* __restrict__ w_down, const float* __restrict__ b_down,
    float* __restrict__ out) {
    int e = blockIdx.y >> 6;
    int t = blockIdx.y & 63;
    int cnt = g_cnt[e];
    int m0 = t * TM;
    if (m0 >= cnt) return;
    int base = g_off[e] + m0;
    int valid = min(TM, cnt - m0);
    int h0 = blockIdx.x * TN;

    __shared__ float Ps[TM][TK + 1];
    __shared__ float Ds[TK][TN + 4];
    __shared__ int toks[TM];
    __shared__ float rws[TM];

    int tid = threadIdx.x;
    if (tid < TM) {
        int r = base + min(tid, valid - 1);
        toks[tid] = g_row_tok[r];
        rws[tid] = g_row_w[r];
    }
    __syncthreads();

    const float* Wd = w_down + (size_t)e * FDIM * HDIM;

    float acc[4][4];
#pragma unroll
    for (int i = 0; i < 4; i++)
#pragma unroll
        for (int j = 0; j < 4; j++) acc[i][j] = 0.f;

    int tx = tid & 15, ty = tid >> 4;

    for (int k0 = 0; k0 < FDIM; k0 += TK) {
#pragma unroll
        for (int i = 0; i < 4; i++) {
            int li = tid + 256 * i;
            int m = li >> 4, k = li & 15;
            // CLAMP: rows beyond `valid` must not read past g_phi.
            int row = base + min(m, valid - 1);
            Ps[m][k] = g_phi[(size_t)row * FDIM + k0 + k];
        }
#pragma unroll
        for (int i = 0; i < 4; i++) {
            int li = tid + 256 * i;
            int k = li >> 6, h = li & 63;
            Ds[k][h] = Wd[(size_t)(k0 + k) * HDIM + h0 + h];
        }
        __syncthreads();
#pragma unroll
        for (int kk = 0; kk < TK; kk++) {
            float a[4];
#pragma unroll
            for (int i = 0; i < 4; i++) a[i] = Ps[ty * 4 + i][kk];
            float4 b = *reinterpret_cast<const float4*>(&Ds[kk][tx * 4]);
#pragma unroll
            for (int i = 0; i < 4; i++) {
                acc[i][0] += a[i] * b.x; acc[i][1] += a[i] * b.y;
                acc[i][2] += a[i] * b.z; acc[i][3] += a[i] * b.w;
            }
        }
        __syncthreads();
    }

#pragma unroll
    for (int i = 0; i < 4; i++) {
        int m = ty * 4 + i;
        if (m >= valid) continue;
        int token = toks[m];
        float w = rws[m];
        float* orow = out + (size_t)token * HDIM + h0;
#pragma unroll
        for (int j = 0; j < 4; j++) {
            int h = tx * 4 + j;
            float y = acc[i][j] + b_down[e * HDIM + h0 + h];
            atomicAdd(&orow[h], w * y);
        }
    }
}

// ---------------------------------------------------------------
extern "C" void kernel_launch(void* const* d_in, const int* in_sizes, int n_in,
                              void* d_out, int out_size) {
    const float* x      = (const float*)d_in[0];  // [2,2048,1024]
    const float* gate_w = (const float*)d_in[1];  // [8,1024]
    const float* w_up   = (const float*)d_in[2];  // [8,1024,2048]
    const float* w_gate = (const float*)d_in[3];  // [8,1024,2048]
    const float* w_down = (const float*)d_in[4];  // [8,2048,1024]
    const float* b_up   = (const float*)d_in[5];  // [8,2048]
    const float* b_gate = (const float*)d_in[6];  // [8,2048]
    const float* b_down = (const float*)d_in[7];  // [8,1024]

    float* out = (float*)d_out;                   // [N, H] then logits [N, E]
    float* rl  = out + (size_t)NTOK * HDIM;

    init_kernel<<<1024, 256>>>(out);
    router_kernel<<<NTOK / 4, 128>>>(x, gate_w, rl);
    scan_kernel<<<1, 32>>>();
    scatter_kernel<<<NTOK / 256, 256>>>();

    dim3 gridA(FDIM / TN, EXPE * 64);
    up_gate_kernel<<<gridA, 256>>>(x, w_up, w_gate, b_up, b_gate);

    dim3 gridB(HDIM / TN, EXPE * 64);
    down_kernel<<<gridB, 256>>>(w_down, b_down, out);
}

// round 9
// speedup vs baseline: 2.1666x; 2.1666x over previous
#include <cuda_runtime.h>
#include <cuda_bf16.h>
#include <cstdint>

#define NTOK 4096
#define HDIM 1024
#define FDIM 2048
#define EXPE 8
#define NPAIR (NTOK * 2)

// ================= scratch (static device globals) =================
__device__ __nv_bfloat16 g_xhi[(size_t)NTOK * HDIM];
__device__ __nv_bfloat16 g_xlo[(size_t)NTOK * HDIM];
// transposed weights: K (=H or F) contiguous
__device__ __nv_bfloat16 g_wut_hi[(size_t)EXPE * FDIM * HDIM]; // [E][F][H]
__device__ __nv_bfloat16 g_wut_lo[(size_t)EXPE * FDIM * HDIM];
__device__ __nv_bfloat16 g_wgt_hi[(size_t)EXPE * FDIM * HDIM];
__device__ __nv_bfloat16 g_wgt_lo[(size_t)EXPE * FDIM * HDIM];
__device__ __nv_bfloat16 g_wdt_hi[(size_t)EXPE * HDIM * FDIM]; // [E][H][F]
__device__ __nv_bfloat16 g_wdt_lo[(size_t)EXPE * HDIM * FDIM];
__device__ __nv_bfloat16 g_phi_hi[(size_t)NPAIR * FDIM];
__device__ __nv_bfloat16 g_phi_lo[(size_t)NPAIR * FDIM];
__device__ int   g_cnt[EXPE];
__device__ int   g_off[EXPE + 1];
__device__ int   g_cur[EXPE];
__device__ int   g_tok_e[NTOK * 2];
__device__ float g_tok_w[NTOK * 2];
__device__ int   g_row_tok[NPAIR];
__device__ float g_row_w[NPAIR];

__device__ __forceinline__ uint32_t smem_u32(const void* p) {
    uint32_t a;
    asm("{ .reg .u64 t; cvta.to.shared.u64 t, %1; cvt.u32.u64 %0, t; }"
        : "=r"(a) : "l"(p));
    return a;
}

// mma.sync bf16 (sm_80+ baseline PTX)
#define MMA_BF16(acc, a, b0, b1)                                                \
    asm volatile(                                                               \
        "mma.sync.aligned.m16n8k16.row.col.f32.bf16.bf16.f32 "                  \
        "{%0,%1,%2,%3}, {%4,%5,%6,%7}, {%8,%9}, {%0,%1,%2,%3};"                 \
        : "+f"((acc)[0]), "+f"((acc)[1]), "+f"((acc)[2]), "+f"((acc)[3])        \
        : "r"((a)[0]), "r"((a)[1]), "r"((a)[2]), "r"((a)[3]), "r"(b0), "r"(b1))

// ldmatrix x4: HW-defined fragment distribution from per-lane ROW addresses.
#define LDMX4(r, addr)                                                          \
    asm volatile("ldmatrix.sync.aligned.m8n8.x4.shared.b16 {%0,%1,%2,%3}, [%4];"\
        : "=r"((r)[0]), "=r"((r)[1]), "=r"((r)[2]), "=r"((r)[3]) : "r"(addr))

__device__ __forceinline__ uint32_t pack_hi_lo(float v0, float v1,
                                               uint32_t& lo_pack) {
    __nv_bfloat16 h0 = __float2bfloat16(v0);
    __nv_bfloat16 h1 = __float2bfloat16(v1);
    __nv_bfloat16 l0 = __float2bfloat16(v0 - __bfloat162float(h0));
    __nv_bfloat16 l1 = __float2bfloat16(v1 - __bfloat162float(h1));
    lo_pack = (uint32_t)__bfloat16_as_ushort(l0) |
              ((uint32_t)__bfloat16_as_ushort(l1) << 16);
    return (uint32_t)__bfloat16_as_ushort(h0) |
           ((uint32_t)__bfloat16_as_ushort(h1) << 16);
}

// ================= 0) init =================
__global__ void init_kernel(float* __restrict__ out) {
    int tid = blockIdx.x * blockDim.x + threadIdx.x;
    if (tid < EXPE) g_cnt[tid] = 0;
    const int total = NTOK * HDIM;
    for (int i = tid * 4; i < total; i += gridDim.x * blockDim.x * 4)
        *reinterpret_cast<float4*>(out + i) = make_float4(0.f, 0.f, 0.f, 0.f);
}

// ================= 1) router =================
__global__ void router_kernel(const float* __restrict__ x,
                              const float* __restrict__ gw,
                              float* __restrict__ rl_out) {
    __shared__ float sgw[EXPE * HDIM];
    int tid = threadIdx.x;
    for (int i = tid; i < EXPE * HDIM; i += 128) sgw[i] = gw[i];
    __syncthreads();

    int warp = tid >> 5, lane = tid & 31;
    int n = blockIdx.x * 4 + warp;
    if (n >= NTOK) return;
    const float* xr = x + (size_t)n * HDIM;

    float acc[EXPE];
#pragma unroll
    for (int e = 0; e < EXPE; e++) acc[e] = 0.f;
    for (int h = lane; h < HDIM; h += 32) {
        float xv = xr[h];
#pragma unroll
        for (int e = 0; e < EXPE; e++) acc[e] += xv * sgw[e * HDIM + h];
    }
#pragma unroll
    for (int e = 0; e < EXPE; e++)
#pragma unroll
        for (int o = 16; o > 0; o >>= 1)
            acc[e] += __shfl_xor_sync(0xffffffffu, acc[e], o);

    if (lane == 0) {
#pragma unroll
        for (int e = 0; e < EXPE; e++) rl_out[(size_t)n * EXPE + e] = acc[e];
        float m = acc[0];
#pragma unroll
        for (int e = 1; e < EXPE; e++) m = fmaxf(m, acc[e]);
        float p[EXPE];
#pragma unroll
        for (int e = 0; e < EXPE; e++) p[e] = __expf(acc[e] - m);
        int i0 = 0;
#pragma unroll
        for (int e = 1; e < EXPE; e++) if (p[e] > p[i0]) i0 = e;
        int i1 = (i0 == 0) ? 1 : 0;
#pragma unroll
        for (int e = 0; e < EXPE; e++)
            if (e != i0 && p[e] > p[i1]) i1 = e;
        float s2 = p[i0] + p[i1];
        g_tok_e[n * 2 + 0] = i0; g_tok_w[n * 2 + 0] = p[i0] / s2;
        g_tok_e[n * 2 + 1] = i1; g_tok_w[n * 2 + 1] = p[i1] / s2;
        atomicAdd(&g_cnt[i0], 1);
        atomicAdd(&g_cnt[i1], 1);
    }
}

// ================= 2) scan =================
__global__ void scan_kernel() {
    if (threadIdx.x == 0 && blockIdx.x == 0) {
        int acc = 0;
        for (int e = 0; e < EXPE; e++) {
            g_off[e] = acc; g_cur[e] = acc; acc += g_cnt[e];
        }
        g_off[EXPE] = acc;
    }
}

// ================= 3) scatter =================
__global__ void scatter_kernel() {
    int n = blockIdx.x * blockDim.x + threadIdx.x;
    if (n >= NTOK) return;
#pragma unroll
    for (int k = 0; k < 2; k++) {
        int e = g_tok_e[n * 2 + k];
        int pos = atomicAdd(&g_cur[e], 1);
        g_row_tok[pos] = n;
        g_row_w[pos] = g_tok_w[n * 2 + k];
    }
}

// ================= 4) split x into bf16 hi/lo =================
__global__ void split_x_kernel(const float* __restrict__ x) {
    int i = blockIdx.x * blockDim.x + threadIdx.x;
    float4 v = reinterpret_cast<const float4*>(x)[i];
    float vv[4] = {v.x, v.y, v.z, v.w};
    uint32_t hh[2], ll[2];
#pragma unroll
    for (int j = 0; j < 2; j++)
        hh[j] = pack_hi_lo(vv[j * 2], vv[j * 2 + 1], ll[j]);
    reinterpret_cast<uint2*>(g_xhi)[i] = make_uint2(hh[0], hh[1]);
    reinterpret_cast<uint2*>(g_xlo)[i] = make_uint2(ll[0], ll[1]);
}

// ================= 5) transpose + split weights =================
// BUG FIX (round 8): destination device globals must be bound INSIDE device
// code. Passing g_wut_hi etc. as kernel args from host code takes the HOST
// shadow symbol address; with ATS on GB300 the writes silently land in host
// memory and the device arrays stay zero (-> exact-zero output, rel_err=1.0).
__global__ void transpose_split_kernel(const float* __restrict__ src,
                                       int which, int R, int C) {
    __nv_bfloat16* dhi;
    __nv_bfloat16* dlo;
    if (which == 0)      { dhi = g_wut_hi; dlo = g_wut_lo; }
    else if (which == 1) { dhi = g_wgt_hi; dlo = g_wgt_lo; }
    else                 { dhi = g_wdt_hi; dlo = g_wdt_lo; }

    __shared__ float t[32][33];
    int e = blockIdx.z;
    const float* s = src + (size_t)e * R * C;
    int c0 = blockIdx.x * 32, r0 = blockIdx.y * 32;
#pragma unroll
    for (int i = threadIdx.y; i < 32; i += 8)
        t[i][threadIdx.x] = s[(size_t)(r0 + i) * C + c0 + threadIdx.x];
    __syncthreads();
#pragma unroll
    for (int j = threadIdx.y; j < 32; j += 8) {
        float v = t[threadIdx.x][j];
        __nv_bfloat16 h = __float2bfloat16(v);
        __nv_bfloat16 l = __float2bfloat16(v - __bfloat162float(h));
        size_t o = ((size_t)e * C + c0 + j) * R + r0 + threadIdx.x;
        dhi[o] = h;
        dlo[o] = l;
    }
}

// ================= 6) up+gate mma.sync GEMM (ldmatrix frags) ==========
// block: 128 rows x 64 f, BK=32. 8 warps: 4 (m) x 2 (n). warp tile 32x32.
#define S 40   // padded smem stride (elements)

__global__ __launch_bounds__(256) void up_gate_mma(
    const float* __restrict__ b_up, const float* __restrict__ b_gate) {
    __shared__ __nv_bfloat16 Ah[128 * S], Al[128 * S];
    __shared__ __nv_bfloat16 Buh[64 * S], Bul[64 * S], Bgh[64 * S], Bgl[64 * S];
    __shared__ int toks[128];

    int e = blockIdx.y >> 5;
    int t = blockIdx.y & 31;
    int cnt = g_cnt[e];
    int m0 = t * 128;
    if (m0 >= cnt) return;
    int base = g_off[e] + m0;
    int valid = min(128, cnt - m0);
    int f0 = blockIdx.x * 64;

    int tid = threadIdx.x;
    if (tid < 128) toks[tid] = g_row_tok[base + min(tid, valid - 1)];
    __syncthreads();

    const __nv_bfloat16* WUh = g_wut_hi + ((size_t)e * FDIM + f0) * HDIM;
    const __nv_bfloat16* WUl = g_wut_lo + ((size_t)e * FDIM + f0) * HDIM;
    const __nv_bfloat16* WGh = g_wgt_hi + ((size_t)e * FDIM + f0) * HDIM;
    const __nv_bfloat16* WGl = g_wgt_lo + ((size_t)e * FDIM + f0) * HDIM;

    int wid = tid >> 5, lane = tid & 31;
    int wm = wid & 3, wn = wid >> 2;
    int grp = lane >> 2, qid = lane & 3;

    uint32_t AhB = smem_u32(Ah), AlB = smem_u32(Al);
    uint32_t UhB = smem_u32(Buh), UlB = smem_u32(Bul);
    uint32_t GhB = smem_u32(Bgh), GlB = smem_u32(Bgl);
    int arow = wm * 32 + (lane & 15);          // + mf*16
    int acol = (lane >> 4) * 8;                // + ks*16
    int brow = wn * 32 + ((lane >> 4) & 1) * 8 + (lane & 7);  // + p*16
    int bcol = ((lane >> 3) & 1) * 8;          // + ks*16

    float accU[2][4][4], accG[2][4][4];
#pragma unroll
    for (int a = 0; a < 2; a++)
#pragma unroll
        for (int b = 0; b < 4; b++)
#pragma unroll
            for (int c = 0; c < 4; c++) { accU[a][b][c] = 0.f; accG[a][b][c] = 0.f; }

    for (int k0 = 0; k0 < HDIM; k0 += 32) {
#pragma unroll
        for (int i = 0; i < 2; i++) {
            int u = tid + i * 256;
            int r = u >> 2, sg = u & 3;
            size_t src = (size_t)toks[r] * HDIM + k0;
            *reinterpret_cast<uint4*>(&Ah[r * S + sg * 8]) =
                *(reinterpret_cast<const uint4*>(g_xhi + src) + sg);
            *reinterpret_cast<uint4*>(&Al[r * S + sg * 8]) =
                *(reinterpret_cast<const uint4*>(g_xlo + src) + sg);
        }
        {
            int r = tid >> 2, sg = tid & 3;
            size_t wo = (size_t)r * HDIM + k0;
            *reinterpret_cast<uint4*>(&Buh[r * S + sg * 8]) =
                *(reinterpret_cast<const uint4*>(WUh + wo) + sg);
            *reinterpret_cast<uint4*>(&Bul[r * S + sg * 8]) =
                *(reinterpret_cast<const uint4*>(WUl + wo) + sg);
            *reinterpret_cast<uint4*>(&Bgh[r * S + sg * 8]) =
                *(reinterpret_cast<const uint4*>(WGh + wo) + sg);
            *reinterpret_cast<uint4*>(&Bgl[r * S + sg * 8]) =
                *(reinterpret_cast<const uint4*>(WGl + wo) + sg);
        }
        __syncthreads();

#pragma unroll
        for (int ks = 0; ks < 2; ks++) {
            uint32_t ah[2][4], al[2][4];
#pragma unroll
            for (int mf = 0; mf < 2; mf++) {
                uint32_t ao = (uint32_t)(((arow + mf * 16) * S + ks * 16 + acol) * 2);
                LDMX4(ah[mf], AhB + ao);
                LDMX4(al[mf], AlB + ao);
            }
            uint32_t uh[8], ul[8], gh[8], gl[8];
#pragma unroll
            for (int p = 0; p < 2; p++) {
                uint32_t bo = (uint32_t)(((brow + p * 16) * S + ks * 16 + bcol) * 2);
                LDMX4(uh + p * 4, UhB + bo);
                LDMX4(ul + p * 4, UlB + bo);
                LDMX4(gh + p * 4, GhB + bo);
                LDMX4(gl + p * 4, GlB + bo);
            }
#pragma unroll
            for (int nf = 0; nf < 4; nf++) {
                uint32_t u0 = uh[nf * 2], u1 = uh[nf * 2 + 1];
                uint32_t w0 = ul[nf * 2], w1 = ul[nf * 2 + 1];
                uint32_t g0 = gh[nf * 2], g1 = gh[nf * 2 + 1];
                uint32_t h0 = gl[nf * 2], h1 = gl[nf * 2 + 1];
#pragma unroll
                for (int mf = 0; mf < 2; mf++) {
                    MMA_BF16(accU[mf][nf], ah[mf], u0, u1);
                    MMA_BF16(accU[mf][nf], ah[mf], w0, w1);
                    MMA_BF16(accU[mf][nf], al[mf], u0, u1);
                    MMA_BF16(accG[mf][nf], ah[mf], g0, g1);
                    MMA_BF16(accG[mf][nf], ah[mf], h0, h1);
                    MMA_BF16(accG[mf][nf], al[mf], g0, g1);
                }
            }
        }
        __syncthreads();
    }

    // epilogue: phi = silu(v)*u, split to bf16 hi/lo
#pragma unroll
    for (int mf = 0; mf < 2; mf++) {
#pragma unroll
        for (int half = 0; half < 2; half++) {
            int mloc = wm * 32 + mf * 16 + grp + half * 8;
            if (mloc >= valid) continue;
            size_t row = (size_t)(base + mloc);
#pragma unroll
            for (int nf = 0; nf < 4; nf++) {
                int fc = f0 + wn * 32 + nf * 8 + qid * 2;
                float u0 = accU[mf][nf][half * 2 + 0] + __ldg(b_up + e * FDIM + fc);
                float u1 = accU[mf][nf][half * 2 + 1] + __ldg(b_up + e * FDIM + fc + 1);
                float v0 = accG[mf][nf][half * 2 + 0] + __ldg(b_gate + e * FDIM + fc);
                float v1 = accG[mf][nf][half * 2 + 1] + __ldg(b_gate + e * FDIM + fc + 1);
                float p0 = (v0 / (1.f + __expf(-v0))) * u0;
                float p1 = (v1 / (1.f + __expf(-v1))) * u1;
                uint32_t lo;
                uint32_t hi = pack_hi_lo(p0, p1, lo);
                *reinterpret_cast<uint32_t*>(g_phi_hi + row * FDIM + fc) = hi;
                *reinterpret_cast<uint32_t*>(g_phi_lo + row * FDIM + fc) = lo;
            }
        }
    }
}

// ================= 7) down mma.sync GEMM + combine (ldmatrix) =========
// block: 128 rows x 128 h, BK=32. 8 warps: 2 (m) x 4 (n). warp tile 64x32.
__global__ __launch_bounds__(256) void down_mma(
    const float* __restrict__ b_down, float* __restrict__ out) {
    __shared__ __nv_bfloat16 Ah[128 * S], Al[128 * S];
    __shared__ __nv_bfloat16 Bh[128 * S], Bl[128 * S];
    __shared__ int   toks[128];
    __shared__ float rws[128];

    int e = blockIdx.y >> 5;
    int t = blockIdx.y & 31;
    int cnt = g_cnt[e];
    int m0 = t * 128;
    if (m0 >= cnt) return;
    int base = g_off[e] + m0;
    int valid = min(128, cnt - m0);
    int h0 = blockIdx.x * 128;

    int tid = threadIdx.x;
    if (tid < 128) {
        int r = base + min(tid, valid - 1);
        toks[tid] = g_row_tok[r];
        rws[tid]  = g_row_w[r];
    }
    __syncthreads();

    const __nv_bfloat16* WDh = g_wdt_hi + ((size_t)e * HDIM + h0) * FDIM;
    const __nv_bfloat16* WDl = g_wdt_lo + ((size_t)e * HDIM + h0) * FDIM;

    int wid = tid >> 5, lane = tid & 31;
    int wm = wid & 1, wn = wid >> 1;
    int grp = lane >> 2, qid = lane & 3;

    uint32_t AhB = smem_u32(Ah), AlB = smem_u32(Al);
    uint32_t BhB = smem_u32(Bh), BlB = smem_u32(Bl);
    int arow = wm * 64 + (lane & 15);          // + mf*16
    int acol = (lane >> 4) * 8;                // + ks*16
    int brow = wn * 32 + ((lane >> 4) & 1) * 8 + (lane & 7);  // + p*16
    int bcol = ((lane >> 3) & 1) * 8;          // + ks*16

    float acc[4][4][4];
#pragma unroll
    for (int a = 0; a < 4; a++)
#pragma unroll
        for (int b = 0; b < 4; b++)
#pragma unroll
            for (int c = 0; c < 4; c++) acc[a][b][c] = 0.f;

    for (int k0 = 0; k0 < FDIM; k0 += 32) {
#pragma unroll
        for (int i = 0; i < 2; i++) {
            int u = tid + i * 256;
            int r = u >> 2, sg = u & 3;
            size_t src = (size_t)(base + min(r, valid - 1)) * FDIM + k0;
            *reinterpret_cast<uint4*>(&Ah[r * S + sg * 8]) =
                *(reinterpret_cast<const uint4*>(g_phi_hi + src) + sg);
            *reinterpret_cast<uint4*>(&Al[r * S + sg * 8]) =
                *(reinterpret_cast<const uint4*>(g_phi_lo + src) + sg);
            size_t wo = (size_t)r * FDIM + k0;
            *reinterpret_cast<uint4*>(&Bh[r * S + sg * 8]) =
                *(reinterpret_cast<const uint4*>(WDh + wo) + sg);
            *reinterpret_cast<uint4*>(&Bl[r * S + sg * 8]) =
                *(reinterpret_cast<const uint4*>(WDl + wo) + sg);
        }
        __syncthreads();

#pragma unroll
        for (int ks = 0; ks < 2; ks++) {
            uint32_t ah[4][4], al[4][4];
#pragma unroll
            for (int mf = 0; mf < 4; mf++) {
                uint32_t ao = (uint32_t)(((arow + mf * 16) * S + ks * 16 + acol) * 2);
                LDMX4(ah[mf], AhB + ao);
                LDMX4(al[mf], AlB + ao);
            }
            uint32_t bh[8], bl[8];
#pragma unroll
            for (int p = 0; p < 2; p++) {
                uint32_t bo = (uint32_t)(((brow + p * 16) * S + ks * 16 + bcol) * 2);
                LDMX4(bh + p * 4, BhB + bo);
                LDMX4(bl + p * 4, BlB + bo);
            }
#pragma unroll
            for (int nf = 0; nf < 4; nf++) {
                uint32_t b0 = bh[nf * 2], b1 = bh[nf * 2 + 1];
                uint32_t c0 = bl[nf * 2], c1 = bl[nf * 2 + 1];
#pragma unroll
                for (int mf = 0; mf < 4; mf++) {
                    MMA_BF16(acc[mf][nf], ah[mf], b0, b1);
                    MMA_BF16(acc[mf][nf], ah[mf], c0, c1);
                    MMA_BF16(acc[mf][nf], al[mf], b0, b1);
                }
            }
        }
        __syncthreads();
    }

    // epilogue: out[token] += w * (acc + b_down)
#pragma unroll
    for (int mf = 0; mf < 4; mf++) {
#pragma unroll
        for (int half = 0; half < 2; half++) {
            int mloc = wm * 64 + mf * 16 + grp + half * 8;
            if (mloc >= valid) continue;
            int token = toks[mloc];
            float w = rws[mloc];
            float* orow = out + (size_t)token * HDIM;
#pragma unroll
            for (int nf = 0; nf < 4; nf++) {
                int hc = h0 + wn * 32 + nf * 8 + qid * 2;
                float y0 = acc[mf][nf][half * 2 + 0] + __ldg(b_down + e * HDIM + hc);
                float y1 = acc[mf][nf][half * 2 + 1] + __ldg(b_down + e * HDIM + hc + 1);
                atomicAdd(orow + hc,     w * y0);
                atomicAdd(orow + hc + 1, w * y1);
            }
        }
    }
}

// ================= launch =================
extern "C" void kernel_launch(void* const* d_in, const int* in_sizes, int n_in,
                              void* d_out, int out_size) {
    const float* x      = (const float*)d_in[0];
    const float* gate_w = (const float*)d_in[1];
    const float* w_up   = (const float*)d_in[2];
    const float* w_gate = (const float*)d_in[3];
    const float* w_down = (const float*)d_in[4];
    const float* b_up   = (const float*)d_in[5];
    const float* b_gate = (const float*)d_in[6];
    const float* b_down = (const float*)d_in[7];

    float* out = (float*)d_out;
    float* rl  = out + (size_t)NTOK * HDIM;

    init_kernel<<<1024, 256>>>(out);
    router_kernel<<<NTOK / 4, 128>>>(x, gate_w, rl);
    scan_kernel<<<1, 32>>>();
    scatter_kernel<<<NTOK / 256, 256>>>();

    split_x_kernel<<<(NTOK * HDIM / 4) / 256, 256>>>(x);
    {
        dim3 thr(32, 8);
        dim3 g1(FDIM / 32, HDIM / 32, EXPE);
        transpose_split_kernel<<<g1, thr>>>(w_up,   0, HDIM, FDIM);
        transpose_split_kernel<<<g1, thr>>>(w_gate, 1, HDIM, FDIM);
        dim3 g2(HDIM / 32, FDIM / 32, EXPE);
        transpose_split_kernel<<<g2, thr>>>(w_down, 2, FDIM, HDIM);
    }

    dim3 gridA(FDIM / 64, EXPE * 32);
    up_gate_mma<<<gridA, 256>>>(b_up, b_gate);

    dim3 gridB(HDIM / 128, EXPE * 32);
    down_mma<<<gridB, 256>>>(b_down, out);
}

// round 10
// speedup vs baseline: 2.4908x; 1.1497x over previous
#include <cuda_runtime.h>
#include <cuda_bf16.h>
#include <cstdint>

#define NTOK 4096
#define HDIM 1024
#define FDIM 2048
#define EXPE 8
#define NPAIR (NTOK * 2)

// ================= scratch (static device globals) =================
__device__ __nv_bfloat16 g_xhi[(size_t)NTOK * HDIM];
__device__ __nv_bfloat16 g_xlo[(size_t)NTOK * HDIM];
// transposed weights: K (=H or F) contiguous
__device__ __nv_bfloat16 g_wut_hi[(size_t)EXPE * FDIM * HDIM]; // [E][F][H]
__device__ __nv_bfloat16 g_wut_lo[(size_t)EXPE * FDIM * HDIM];
__device__ __nv_bfloat16 g_wgt_hi[(size_t)EXPE * FDIM * HDIM];
__device__ __nv_bfloat16 g_wgt_lo[(size_t)EXPE * FDIM * HDIM];
__device__ __nv_bfloat16 g_wdt_hi[(size_t)EXPE * HDIM * FDIM]; // [E][H][F]
__device__ __nv_bfloat16 g_wdt_lo[(size_t)EXPE * HDIM * FDIM];
__device__ __nv_bfloat16 g_phi_hi[(size_t)NPAIR * FDIM];
__device__ __nv_bfloat16 g_phi_lo[(size_t)NPAIR * FDIM];
__device__ int   g_cnt[EXPE];
__device__ int   g_off[EXPE + 1];
__device__ int   g_cur[EXPE];
__device__ int   g_tok_e[NTOK * 2];
__device__ float g_tok_w[NTOK * 2];
__device__ int   g_row_tok[NPAIR];
__device__ float g_row_w[NPAIR];

__device__ __forceinline__ uint32_t smem_u32(const void* p) {
    uint32_t a;
    asm("{ .reg .u64 t; cvta.to.shared.u64 t, %1; cvt.u32.u64 %0, t; }"
        : "=r"(a) : "l"(p));
    return a;
}

// mma.sync bf16 (sm_80+ baseline PTX)
#define MMA_BF16(acc, a, b0, b1)                                                \
    asm volatile(                                                               \
        "mma.sync.aligned.m16n8k16.row.col.f32.bf16.bf16.f32 "                  \
        "{%0,%1,%2,%3}, {%4,%5,%6,%7}, {%8,%9}, {%0,%1,%2,%3};"                 \
        : "+f"((acc)[0]), "+f"((acc)[1]), "+f"((acc)[2]), "+f"((acc)[3])        \
        : "r"((a)[0]), "r"((a)[1]), "r"((a)[2]), "r"((a)[3]), "r"(b0), "r"(b1))

#define LDMX4(r, addr)                                                          \
    asm volatile("ldmatrix.sync.aligned.m8n8.x4.shared.b16 {%0,%1,%2,%3}, [%4];"\
        : "=r"((r)[0]), "=r"((r)[1]), "=r"((r)[2]), "=r"((r)[3]) : "r"(addr))

#define CP_ASYNC16(sm, gp)                                                      \
    asm volatile("cp.async.cg.shared.global [%0], [%1], 16;"                    \
                 :: "r"(sm), "l"(gp))
#define CP_COMMIT() asm volatile("cp.async.commit_group;" ::: "memory")
#define CP_WAIT1()  asm volatile("cp.async.wait_group 1;" ::: "memory")
#define CP_WAIT0()  asm volatile("cp.async.wait_group 0;" ::: "memory")

__device__ __forceinline__ uint32_t pack_hi_lo(float v0, float v1,
                                               uint32_t& lo_pack) {
    __nv_bfloat16 h0 = __float2bfloat16(v0);
    __nv_bfloat16 h1 = __float2bfloat16(v1);
    __nv_bfloat16 l0 = __float2bfloat16(v0 - __bfloat162float(h0));
    __nv_bfloat16 l1 = __float2bfloat16(v1 - __bfloat162float(h1));
    lo_pack = (uint32_t)__bfloat16_as_ushort(l0) |
              ((uint32_t)__bfloat16_as_ushort(l1) << 16);
    return (uint32_t)__bfloat16_as_ushort(h0) |
           ((uint32_t)__bfloat16_as_ushort(h1) << 16);
}

// ================= 0) init =================
__global__ void init_kernel(float* __restrict__ out) {
    int tid = blockIdx.x * blockDim.x + threadIdx.x;
    if (tid < EXPE) g_cnt[tid] = 0;
    const int total = NTOK * HDIM;
    for (int i = tid * 4; i < total; i += gridDim.x * blockDim.x * 4)
        *reinterpret_cast<float4*>(out + i) = make_float4(0.f, 0.f, 0.f, 0.f);
}

// ================= 1) router =================
__global__ void router_kernel(const float* __restrict__ x,
                              const float* __restrict__ gw,
                              float* __restrict__ rl_out) {
    __shared__ float sgw[EXPE * HDIM];
    int tid = threadIdx.x;
    for (int i = tid; i < EXPE * HDIM; i += 128) sgw[i] = gw[i];
    __syncthreads();

    int warp = tid >> 5, lane = tid & 31;
    int n = blockIdx.x * 4 + warp;
    if (n >= NTOK) return;
    const float* xr = x + (size_t)n * HDIM;

    float acc[EXPE];
#pragma unroll
    for (int e = 0; e < EXPE; e++) acc[e] = 0.f;
    for (int h = lane; h < HDIM; h += 32) {
        float xv = xr[h];
#pragma unroll
        for (int e = 0; e < EXPE; e++) acc[e] += xv * sgw[e * HDIM + h];
    }
#pragma unroll
    for (int e = 0; e < EXPE; e++)
#pragma unroll
        for (int o = 16; o > 0; o >>= 1)
            acc[e] += __shfl_xor_sync(0xffffffffu, acc[e], o);

    if (lane == 0) {
#pragma unroll
        for (int e = 0; e < EXPE; e++) rl_out[(size_t)n * EXPE + e] = acc[e];
        float m = acc[0];
#pragma unroll
        for (int e = 1; e < EXPE; e++) m = fmaxf(m, acc[e]);
        float p[EXPE];
#pragma unroll
        for (int e = 0; e < EXPE; e++) p[e] = __expf(acc[e] - m);
        int i0 = 0;
#pragma unroll
        for (int e = 1; e < EXPE; e++) if (p[e] > p[i0]) i0 = e;
        int i1 = (i0 == 0) ? 1 : 0;
#pragma unroll
        for (int e = 0; e < EXPE; e++)
            if (e != i0 && p[e] > p[i1]) i1 = e;
        float s2 = p[i0] + p[i1];
        g_tok_e[n * 2 + 0] = i0; g_tok_w[n * 2 + 0] = p[i0] / s2;
        g_tok_e[n * 2 + 1] = i1; g_tok_w[n * 2 + 1] = p[i1] / s2;
        atomicAdd(&g_cnt[i0], 1);
        atomicAdd(&g_cnt[i1], 1);
    }
}

// ================= 2) scan =================
__global__ void scan_kernel() {
    if (threadIdx.x == 0 && blockIdx.x == 0) {
        int acc = 0;
        for (int e = 0; e < EXPE; e++) {
            g_off[e] = acc; g_cur[e] = acc; acc += g_cnt[e];
        }
        g_off[EXPE] = acc;
    }
}

// ================= 3) scatter =================
__global__ void scatter_kernel() {
    int n = blockIdx.x * blockDim.x + threadIdx.x;
    if (n >= NTOK) return;
#pragma unroll
    for (int k = 0; k < 2; k++) {
        int e = g_tok_e[n * 2 + k];
        int pos = atomicAdd(&g_cur[e], 1);
        g_row_tok[pos] = n;
        g_row_w[pos] = g_tok_w[n * 2 + k];
    }
}

// ================= 4) split x into bf16 hi/lo =================
__global__ void split_x_kernel(const float* __restrict__ x) {
    int i = blockIdx.x * blockDim.x + threadIdx.x;
    float4 v = reinterpret_cast<const float4*>(x)[i];
    float vv[4] = {v.x, v.y, v.z, v.w};
    uint32_t hh[2], ll[2];
#pragma unroll
    for (int j = 0; j < 2; j++)
        hh[j] = pack_hi_lo(vv[j * 2], vv[j * 2 + 1], ll[j]);
    reinterpret_cast<uint2*>(g_xhi)[i] = make_uint2(hh[0], hh[1]);
    reinterpret_cast<uint2*>(g_xlo)[i] = make_uint2(ll[0], ll[1]);
}

// ================= 5) transpose + split weights =================
// 64R x 32C tiles; each thread writes a packed uint32 (2 consecutive R
// elements) -> fully coalesced 128B/warp stores for hi and lo.
// Destinations bound in device code (round-8 ATS lesson).
__global__ void transpose_split_kernel(const float* __restrict__ src,
                                       int which, int R, int C) {
    __nv_bfloat16* dhi;
    __nv_bfloat16* dlo;
    if (which == 0)      { dhi = g_wut_hi; dlo = g_wut_lo; }
    else if (which == 1) { dhi = g_wgt_hi; dlo = g_wgt_lo; }
    else                 { dhi = g_wdt_hi; dlo = g_wdt_lo; }

    __shared__ float t[64][33];
    int e = blockIdx.z;
    const float* s = src + (size_t)e * R * C;
    int c0 = blockIdx.x * 32, r0 = blockIdx.y * 64;
    int tx = threadIdx.x, ty = threadIdx.y;
#pragma unroll
    for (int i = ty; i < 64; i += 8)
        t[i][tx] = s[(size_t)(r0 + i) * C + c0 + tx];
    __syncthreads();
#pragma unroll
    for (int j = ty; j < 32; j += 8) {
        float v0 = t[2 * tx][j];
        float v1 = t[2 * tx + 1][j];
        uint32_t lo;
        uint32_t hi = pack_hi_lo(v0, v1, lo);
        size_t o = ((size_t)e * C + c0 + j) * R + r0 + 2 * tx;
        *reinterpret_cast<uint32_t*>(dhi + o) = hi;
        *reinterpret_cast<uint32_t*>(dlo + o) = lo;
    }
}

// ================= 6) up+gate mma.sync GEMM (cp.async double-buffer) ==
// block: 128 rows x 64 f, BK=32. 8 warps: 4 (m) x 2 (n). warp tile 32x32.
#define S 40            // padded smem stride (elements)
#define UG_BUF 40960    // Ah Al (10240 ea) + Buh Bul Bgh Bgl (5120 ea)
#define UG_DSM (2 * UG_BUF)

__global__ __launch_bounds__(256) void up_gate_mma(
    const float* __restrict__ b_up, const float* __restrict__ b_gate) {
    extern __shared__ char dynsm[];
    __shared__ int toks[128];

    int e = blockIdx.y >> 5;
    int t = blockIdx.y & 31;
    int cnt = g_cnt[e];
    int m0 = t * 128;
    if (m0 >= cnt) return;
    int base = g_off[e] + m0;
    int valid = min(128, cnt - m0);
    int f0 = blockIdx.x * 64;

    int tid = threadIdx.x;
    if (tid < 128) toks[tid] = g_row_tok[base + min(tid, valid - 1)];
    __syncthreads();

    const __nv_bfloat16* WUh = g_wut_hi + ((size_t)e * FDIM + f0) * HDIM;
    const __nv_bfloat16* WUl = g_wut_lo + ((size_t)e * FDIM + f0) * HDIM;
    const __nv_bfloat16* WGh = g_wgt_hi + ((size_t)e * FDIM + f0) * HDIM;
    const __nv_bfloat16* WGl = g_wgt_lo + ((size_t)e * FDIM + f0) * HDIM;

    int wid = tid >> 5, lane = tid & 31;
    int wm = wid & 3, wn = wid >> 2;
    int grp = lane >> 2, qid = lane & 3;

    uint32_t dynB = smem_u32(dynsm);
    int arow = wm * 32 + (lane & 15);
    int acol = (lane >> 4) * 8;
    int brow = wn * 32 + ((lane >> 4) & 1) * 8 + (lane & 7);
    int bcol = ((lane >> 3) & 1) * 8;

    auto stage = [&](int buf, int k0) {
        uint32_t db = dynB + buf * UG_BUF;
#pragma unroll
        for (int i = 0; i < 2; i++) {
            int u = tid + i * 256;
            int r = u >> 2, sg = u & 3;
            size_t src = (size_t)toks[r] * HDIM + k0 + sg * 8;
            uint32_t so = db + (uint32_t)((r * S + sg * 8) * 2);
            CP_ASYNC16(so,         g_xhi + src);
            CP_ASYNC16(so + 10240, g_xlo + src);
        }
        {
            int r = tid >> 2, sg = tid & 3;
            size_t wo = (size_t)r * HDIM + k0 + sg * 8;
            uint32_t so = db + 20480 + (uint32_t)((r * S + sg * 8) * 2);
            CP_ASYNC16(so,         WUh + wo);
            CP_ASYNC16(so + 5120,  WUl + wo);
            CP_ASYNC16(so + 10240, WGh + wo);
            CP_ASYNC16(so + 15360, WGl + wo);
        }
    };

    float accU[2][4][4], accG[2][4][4];
#pragma unroll
    for (int a = 0; a < 2; a++)
#pragma unroll
        for (int b = 0; b < 4; b++)
#pragma unroll
            for (int c = 0; c < 4; c++) { accU[a][b][c] = 0.f; accG[a][b][c] = 0.f; }

    const int NIT = HDIM / 32;   // 32
    stage(0, 0);
    CP_COMMIT();

    for (int it = 0; it < NIT; it++) {
        if (it + 1 < NIT) {
            stage((it + 1) & 1, (it + 1) * 32);
            CP_COMMIT();
            CP_WAIT1();
        } else {
            CP_WAIT0();
        }
        __syncthreads();

        uint32_t db = dynB + (it & 1) * UG_BUF;
        uint32_t AhB = db, AlB = db + 10240;
        uint32_t UhB = db + 20480, UlB = db + 25600;
        uint32_t GhB = db + 30720, GlB = db + 35840;

#pragma unroll
        for (int ks = 0; ks < 2; ks++) {
            uint32_t ah[2][4], al[2][4];
#pragma unroll
            for (int mf = 0; mf < 2; mf++) {
                uint32_t ao = (uint32_t)(((arow + mf * 16) * S + ks * 16 + acol) * 2);
                LDMX4(ah[mf], AhB + ao);
                LDMX4(al[mf], AlB + ao);
            }
            uint32_t uh[8], ul[8], gh[8], gl[8];
#pragma unroll
            for (int p = 0; p < 2; p++) {
                uint32_t bo = (uint32_t)(((brow + p * 16) * S + ks * 16 + bcol) * 2);
                LDMX4(uh + p * 4, UhB + bo);
                LDMX4(ul + p * 4, UlB + bo);
                LDMX4(gh + p * 4, GhB + bo);
                LDMX4(gl + p * 4, GlB + bo);
            }
#pragma unroll
            for (int nf = 0; nf < 4; nf++) {
                uint32_t u0 = uh[nf * 2], u1 = uh[nf * 2 + 1];
                uint32_t w0 = ul[nf * 2], w1 = ul[nf * 2 + 1];
                uint32_t g0 = gh[nf * 2], g1 = gh[nf * 2 + 1];
                uint32_t h0 = gl[nf * 2], h1 = gl[nf * 2 + 1];
#pragma unroll
                for (int mf = 0; mf < 2; mf++) {
                    MMA_BF16(accU[mf][nf], ah[mf], u0, u1);
                    MMA_BF16(accU[mf][nf], ah[mf], w0, w1);
                    MMA_BF16(accU[mf][nf], al[mf], u0, u1);
                    MMA_BF16(accG[mf][nf], ah[mf], g0, g1);
                    MMA_BF16(accG[mf][nf], ah[mf], h0, h1);
                    MMA_BF16(accG[mf][nf], al[mf], g0, g1);
                }
            }
        }
        __syncthreads();
    }

    // epilogue: phi = silu(v)*u, split to bf16 hi/lo
#pragma unroll
    for (int mf = 0; mf < 2; mf++) {
#pragma unroll
        for (int half = 0; half < 2; half++) {
            int mloc = wm * 32 + mf * 16 + grp + half * 8;
            if (mloc >= valid) continue;
            size_t row = (size_t)(base + mloc);
#pragma unroll
            for (int nf = 0; nf < 4; nf++) {
                int fc = f0 + wn * 32 + nf * 8 + qid * 2;
                float u0 = accU[mf][nf][half * 2 + 0] + __ldg(b_up + e * FDIM + fc);
                float u1 = accU[mf][nf][half * 2 + 1] + __ldg(b_up + e * FDIM + fc + 1);
                float v0 = accG[mf][nf][half * 2 + 0] + __ldg(b_gate + e * FDIM + fc);
                float v1 = accG[mf][nf][half * 2 + 1] + __ldg(b_gate + e * FDIM + fc + 1);
                float p0 = (v0 / (1.f + __expf(-v0))) * u0;
                float p1 = (v1 / (1.f + __expf(-v1))) * u1;
                uint32_t lo;
                uint32_t hi = pack_hi_lo(p0, p1, lo);
                *reinterpret_cast<uint32_t*>(g_phi_hi + row * FDIM + fc) = hi;
                *reinterpret_cast<uint32_t*>(g_phi_lo + row * FDIM + fc) = lo;
            }
        }
    }
}

// ================= 7) down mma.sync GEMM + combine (cp.async) =========
// block: 128 rows x 128 h, BK=32. 8 warps: 2 (m) x 4 (n). warp tile 64x32.
#define DN_BUF 40960    // Ah Al Bh Bl (10240 ea)
#define DN_DSM (2 * DN_BUF)

__global__ __launch_bounds__(256) void down_mma(
    const float* __restrict__ b_down, float* __restrict__ out) {
    extern __shared__ char dynsm[];
    __shared__ int   toks[128];
    __shared__ float rws[128];

    int e = blockIdx.y >> 5;
    int t = blockIdx.y & 31;
    int cnt = g_cnt[e];
    int m0 = t * 128;
    if (m0 >= cnt) return;
    int base = g_off[e] + m0;
    int valid = min(128, cnt - m0);
    int h0 = blockIdx.x * 128;

    int tid = threadIdx.x;
    if (tid < 128) {
        int r = base + min(tid, valid - 1);
        toks[tid] = g_row_tok[r];
        rws[tid]  = g_row_w[r];
    }
    __syncthreads();

    const __nv_bfloat16* WDh = g_wdt_hi + ((size_t)e * HDIM + h0) * FDIM;
    const __nv_bfloat16* WDl = g_wdt_lo + ((size_t)e * HDIM + h0) * FDIM;

    int wid = tid >> 5, lane = tid & 31;
    int wm = wid & 1, wn = wid >> 1;
    int grp = lane >> 2, qid = lane & 3;

    uint32_t dynB = smem_u32(dynsm);
    int arow = wm * 64 + (lane & 15);
    int acol = (lane >> 4) * 8;
    int brow = wn * 32 + ((lane >> 4) & 1) * 8 + (lane & 7);
    int bcol = ((lane >> 3) & 1) * 8;

    auto stage = [&](int buf, int k0) {
        uint32_t db = dynB + buf * DN_BUF;
#pragma unroll
        for (int i = 0; i < 2; i++) {
            int u = tid + i * 256;
            int r = u >> 2, sg = u & 3;
            size_t src = (size_t)(base + min(r, valid - 1)) * FDIM + k0 + sg * 8;
            uint32_t so = db + (uint32_t)((r * S + sg * 8) * 2);
            CP_ASYNC16(so,         g_phi_hi + src);
            CP_ASYNC16(so + 10240, g_phi_lo + src);
            size_t wo = (size_t)r * FDIM + k0 + sg * 8;
            CP_ASYNC16(so + 20480, WDh + wo);
            CP_ASYNC16(so + 30720, WDl + wo);
        }
    };

    float acc[4][4][4];
#pragma unroll
    for (int a = 0; a < 4; a++)
#pragma unroll
        for (int b = 0; b < 4; b++)
#pragma unroll
            for (int c = 0; c < 4; c++) acc[a][b][c] = 0.f;

    const int NIT = FDIM / 32;   // 64
    stage(0, 0);
    CP_COMMIT();

    for (int it = 0; it < NIT; it++) {
        if (it + 1 < NIT) {
            stage((it + 1) & 1, (it + 1) * 32);
            CP_COMMIT();
            CP_WAIT1();
        } else {
            CP_WAIT0();
        }
        __syncthreads();

        uint32_t db = dynB + (it & 1) * DN_BUF;
        uint32_t AhB = db, AlB = db + 10240;
        uint32_t BhB = db + 20480, BlB = db + 30720;

#pragma unroll
        for (int ks = 0; ks < 2; ks++) {
            uint32_t ah[4][4], al[4][4];
#pragma unroll
            for (int mf = 0; mf < 4; mf++) {
                uint32_t ao = (uint32_t)(((arow + mf * 16) * S + ks * 16 + acol) * 2);
                LDMX4(ah[mf], AhB + ao);
                LDMX4(al[mf], AlB + ao);
            }
            uint32_t bh[8], bl[8];
#pragma unroll
            for (int p = 0; p < 2; p++) {
                uint32_t bo = (uint32_t)(((brow + p * 16) * S + ks * 16 + bcol) * 2);
                LDMX4(bh + p * 4, BhB + bo);
                LDMX4(bl + p * 4, BlB + bo);
            }
#pragma unroll
            for (int nf = 0; nf < 4; nf++) {
                uint32_t b0 = bh[nf * 2], b1 = bh[nf * 2 + 1];
                uint32_t c0 = bl[nf * 2], c1 = bl[nf * 2 + 1];
#pragma unroll
                for (int mf = 0; mf < 4; mf++) {
                    MMA_BF16(acc[mf][nf], ah[mf], b0, b1);
                    MMA_BF16(acc[mf][nf], ah[mf], c0, c1);
                    MMA_BF16(acc[mf][nf], al[mf], b0, b1);
                }
            }
        }
        __syncthreads();
    }

    // epilogue: out[token] += w * (acc + b_down)
#pragma unroll
    for (int mf = 0; mf < 4; mf++) {
#pragma unroll
        for (int half = 0; half < 2; half++) {
            int mloc = wm * 64 + mf * 16 + grp + half * 8;
            if (mloc >= valid) continue;
            int token = toks[mloc];
            float w = rws[mloc];
            float* orow = out + (size_t)token * HDIM;
#pragma unroll
            for (int nf = 0; nf < 4; nf++) {
                int hc = h0 + wn * 32 + nf * 8 + qid * 2;
                float y0 = acc[mf][nf][half * 2 + 0] + __ldg(b_down + e * HDIM + hc);
                float y1 = acc[mf][nf][half * 2 + 1] + __ldg(b_down + e * HDIM + hc + 1);
                atomicAdd(orow + hc,     w * y0);
                atomicAdd(orow + hc + 1, w * y1);
            }
        }
    }
}

// ================= launch =================
extern "C" void kernel_launch(void* const* d_in, const int* in_sizes, int n_in,
                              void* d_out, int out_size) {
    const float* x      = (const float*)d_in[0];
    const float* gate_w = (const float*)d_in[1];
    const float* w_up   = (const float*)d_in[2];
    const float* w_gate = (const float*)d_in[3];
    const float* w_down = (const float*)d_in[4];
    const float* b_up   = (const float*)d_in[5];
    const float* b_gate = (const float*)d_in[6];
    const float* b_down = (const float*)d_in[7];

    float* out = (float*)d_out;
    float* rl  = out + (size_t)NTOK * HDIM;

    // >48KB dynamic smem opt-in (deterministic, no allocation, no sync)
    cudaFuncSetAttribute(up_gate_mma,
                         cudaFuncAttributeMaxDynamicSharedMemorySize, UG_DSM);
    cudaFuncSetAttribute(down_mma,
                         cudaFuncAttributeMaxDynamicSharedMemorySize, DN_DSM);

    init_kernel<<<1024, 256>>>(out);
    router_kernel<<<NTOK / 4, 128>>>(x, gate_w, rl);
    scan_kernel<<<1, 32>>>();
    scatter_kernel<<<NTOK / 256, 256>>>();

    split_x_kernel<<<(NTOK * HDIM / 4) / 256, 256>>>(x);
    {
        dim3 thr(32, 8);
        dim3 g1(FDIM / 32, HDIM / 64, EXPE);
        transpose_split_kernel<<<g1, thr>>>(w_up,   0, HDIM, FDIM);
        transpose_split_kernel<<<g1, thr>>>(w_gate, 1, HDIM, FDIM);
        dim3 g2(HDIM / 32, FDIM / 64, EXPE);
        transpose_split_kernel<<<g2, thr>>>(w_down, 2, FDIM, HDIM);
    }

    dim3 gridA(FDIM / 64, EXPE * 32);
    up_gate_mma<<<gridA, 256, UG_DSM>>>(b_up, b_gate);

    dim3 gridB(HDIM / 128, EXPE * 32);
    down_mma<<<gridB, 256, DN_DSM>>>(b_down, out);
}

// round 12
// speedup vs baseline: 3.9376x; 1.5808x over previous
#include <cuda_runtime.h>
#include <cuda_fp16.h>
#include <cstdint>

#define NTOK 4096
#define HDIM 1024
#define FDIM 2048
#define EXPE 8
#define NPAIR (NTOK * 2)

// ================= scratch (static device globals) =================
__device__ __half g_xhi[(size_t)NTOK * HDIM];
__device__ __half g_xlo[(size_t)NTOK * HDIM];
// transposed weights (single fp16): K (=H or F) contiguous
__device__ __half g_wut[(size_t)EXPE * FDIM * HDIM]; // [E][F][H]
__device__ __half g_wgt[(size_t)EXPE * FDIM * HDIM];
__device__ __half g_wdt[(size_t)EXPE * HDIM * FDIM]; // [E][H][F]
__device__ __half g_phi_hi[(size_t)NPAIR * FDIM];
__device__ __half g_phi_lo[(size_t)NPAIR * FDIM];
__device__ int   g_cnt[EXPE];
__device__ int   g_off[EXPE + 1];
__device__ int   g_cur[EXPE];
__device__ int   g_tok_e[NTOK * 2];
__device__ float g_tok_w[NTOK * 2];
__device__ int   g_row_tok[NPAIR];
__device__ float g_row_w[NPAIR];

__device__ __forceinline__ uint32_t smem_u32(const void* p) {
    uint32_t a;
    asm("{ .reg .u64 t; cvta.to.shared.u64 t, %1; cvt.u32.u64 %0, t; }"
        : "=r"(a) : "l"(p));
    return a;
}

// mma.sync fp16 in / fp32 acc (sm_80+ baseline PTX)
#define MMA_F16(acc, a, b0, b1)                                                 \
    asm volatile(                                                               \
        "mma.sync.aligned.m16n8k16.row.col.f32.f16.f16.f32 "                    \
        "{%0,%1,%2,%3}, {%4,%5,%6,%7}, {%8,%9}, {%0,%1,%2,%3};"                 \
        : "+f"((acc)[0]), "+f"((acc)[1]), "+f"((acc)[2]), "+f"((acc)[3])        \
        : "r"((a)[0]), "r"((a)[1]), "r"((a)[2]), "r"((a)[3]), "r"(b0), "r"(b1))

#define LDMX4(r, addr)                                                          \
    asm volatile("ldmatrix.sync.aligned.m8n8.x4.shared.b16 {%0,%1,%2,%3}, [%4];"\
        : "=r"((r)[0]), "=r"((r)[1]), "=r"((r)[2]), "=r"((r)[3]) : "r"(addr))

#define CP_ASYNC16(sm, gp)                                                      \
    asm volatile("cp.async.cg.shared.global [%0], [%1], 16;"                    \
                 :: "r"(sm), "l"(gp))
#define CP_COMMIT() asm volatile("cp.async.commit_group;" ::: "memory")
#define CP_WAIT1()  asm volatile("cp.async.wait_group 1;" ::: "memory")
#define CP_WAIT0()  asm volatile("cp.async.wait_group 0;" ::: "memory")

// fp16 2-term split: v = hi + lo, |lo| <= 2^-11 |v|
__device__ __forceinline__ uint32_t pack_hi_lo(float v0, float v1,
                                               uint32_t& lo_pack) {
    __half h0 = __float2half_rn(v0);
    __half h1 = __float2half_rn(v1);
    __half l0 = __float2half_rn(v0 - __half2float(h0));
    __half l1 = __float2half_rn(v1 - __half2float(h1));
    lo_pack = (uint32_t)__half_as_ushort(l0) |
              ((uint32_t)__half_as_ushort(l1) << 16);
    return (uint32_t)__half_as_ushort(h0) |
           ((uint32_t)__half_as_ushort(h1) << 16);
}

// ================= 0) init =================
__global__ void init_kernel(float* __restrict__ out) {
    int tid = blockIdx.x * blockDim.x + threadIdx.x;
    if (tid < EXPE) g_cnt[tid] = 0;
    const int total = NTOK * HDIM;
    for (int i = tid * 4; i < total; i += gridDim.x * blockDim.x * 4)
        *reinterpret_cast<float4*>(out + i) = make_float4(0.f, 0.f, 0.f, 0.f);
}

// ================= 1) router =================
__global__ void router_kernel(const float* __restrict__ x,
                              const float* __restrict__ gw,
                              float* __restrict__ rl_out) {
    __shared__ float sgw[EXPE * HDIM];
    int tid = threadIdx.x;
    for (int i = tid; i < EXPE * HDIM; i += 128) sgw[i] = gw[i];
    __syncthreads();

    int warp = tid >> 5, lane = tid & 31;
    int n = blockIdx.x * 4 + warp;
    if (n >= NTOK) return;
    const float* xr = x + (size_t)n * HDIM;

    float acc[EXPE];
#pragma unroll
    for (int e = 0; e < EXPE; e++) acc[e] = 0.f;
    for (int h = lane; h < HDIM; h += 32) {
        float xv = xr[h];
#pragma unroll
        for (int e = 0; e < EXPE; e++) acc[e] += xv * sgw[e * HDIM + h];
    }
#pragma unroll
    for (int e = 0; e < EXPE; e++)
#pragma unroll
        for (int o = 16; o > 0; o >>= 1)
            acc[e] += __shfl_xor_sync(0xffffffffu, acc[e], o);

    if (lane == 0) {
#pragma unroll
        for (int e = 0; e < EXPE; e++) rl_out[(size_t)n * EXPE + e] = acc[e];
        float m = acc[0];
#pragma unroll
        for (int e = 1; e < EXPE; e++) m = fmaxf(m, acc[e]);
        float p[EXPE];
#pragma unroll
        for (int e = 0; e < EXPE; e++) p[e] = __expf(acc[e] - m);
        int i0 = 0;
#pragma unroll
        for (int e = 1; e < EXPE; e++) if (p[e] > p[i0]) i0 = e;
        int i1 = (i0 == 0) ? 1 : 0;
#pragma unroll
        for (int e = 0; e < EXPE; e++)
            if (e != i0 && p[e] > p[i1]) i1 = e;
        float s2 = p[i0] + p[i1];
        g_tok_e[n * 2 + 0] = i0; g_tok_w[n * 2 + 0] = p[i0] / s2;
        g_tok_e[n * 2 + 1] = i1; g_tok_w[n * 2 + 1] = p[i1] / s2;
        atomicAdd(&g_cnt[i0], 1);
        atomicAdd(&g_cnt[i1], 1);
    }
}

// ================= 2) scan =================
__global__ void scan_kernel() {
    if (threadIdx.x == 0 && blockIdx.x == 0) {
        int acc = 0;
        for (int e = 0; e < EXPE; e++) {
            g_off[e] = acc; g_cur[e] = acc; acc += g_cnt[e];
        }
        g_off[EXPE] = acc;
    }
}

// ================= 3) scatter =================
__global__ void scatter_kernel() {
    int n = blockIdx.x * blockDim.x + threadIdx.x;
    if (n >= NTOK) return;
#pragma unroll
    for (int k = 0; k < 2; k++) {
        int e = g_tok_e[n * 2 + k];
        int pos = atomicAdd(&g_cur[e], 1);
        g_row_tok[pos] = n;
        g_row_w[pos] = g_tok_w[n * 2 + k];
    }
}

// ================= 4) split x into fp16 hi/lo =================
__global__ void split_x_kernel(const float* __restrict__ x) {
    int i = blockIdx.x * blockDim.x + threadIdx.x;
    float4 v = reinterpret_cast<const float4*>(x)[i];
    float vv[4] = {v.x, v.y, v.z, v.w};
    uint32_t hh[2], ll[2];
#pragma unroll
    for (int j = 0; j < 2; j++)
        hh[j] = pack_hi_lo(vv[j * 2], vv[j * 2 + 1], ll[j]);
    reinterpret_cast<uint2*>(g_xhi)[i] = make_uint2(hh[0], hh[1]);
    reinterpret_cast<uint2*>(g_xlo)[i] = make_uint2(ll[0], ll[1]);
}

// ================= 5) transpose + fp16-convert weights =================
// 64R x 32C tiles; each thread writes a packed uint32 (2 consecutive R
// elements) -> fully coalesced stores. Destinations bound in device code
// (round-8 ATS lesson: never pass __device__ globals as host-side args).
__global__ void transpose_cvt_kernel(const float* __restrict__ src,
                                     int which, int R, int C) {
    __half* dst;
    if (which == 0)      dst = g_wut;
    else if (which == 1) dst = g_wgt;
    else                 dst = g_wdt;

    __shared__ float t[64][33];
    int e = blockIdx.z;
    const float* s = src + (size_t)e * R * C;
    int c0 = blockIdx.x * 32, r0 = blockIdx.y * 64;
    int tx = threadIdx.x, ty = threadIdx.y;
#pragma unroll
    for (int i = ty; i < 64; i += 8)
        t[i][tx] = s[(size_t)(r0 + i) * C + c0 + tx];
    __syncthreads();
#pragma unroll
    for (int j = ty; j < 32; j += 8) {
        __half h0 = __float2half_rn(t[2 * tx][j]);
        __half h1 = __float2half_rn(t[2 * tx + 1][j]);
        uint32_t hp = (uint32_t)__half_as_ushort(h0) |
                      ((uint32_t)__half_as_ushort(h1) << 16);
        size_t o = ((size_t)e * C + c0 + j) * R + r0 + 2 * tx;
        *reinterpret_cast<uint32_t*>(dst + o) = hp;
    }
}

// ================= 6) up+gate mma.sync GEMM (fp16 2-term) =============
// block: 128 rows x 64 f, BK=32. 8 warps: 4 (m) x 2 (n). warp tile 32x32.
#define S 40            // padded smem stride (elements)
#define UG_BUF 30720    // Ah Al (10240 ea) + Bu Bg (5120 ea)
#define UG_DSM (2 * UG_BUF)

__global__ __launch_bounds__(256) void up_gate_mma(
    const float* __restrict__ b_up, const float* __restrict__ b_gate) {
    extern __shared__ char dynsm[];
    __shared__ int toks[128];

    int e = blockIdx.y >> 5;
    int t = blockIdx.y & 31;
    int cnt = g_cnt[e];
    int m0 = t * 128;
    if (m0 >= cnt) return;
    int base = g_off[e] + m0;
    int valid = min(128, cnt - m0);
    int f0 = blockIdx.x * 64;

    int tid = threadIdx.x;
    if (tid < 128) toks[tid] = g_row_tok[base + min(tid, valid - 1)];
    __syncthreads();

    const __half* WU = g_wut + ((size_t)e * FDIM + f0) * HDIM;
    const __half* WG = g_wgt + ((size_t)e * FDIM + f0) * HDIM;

    int wid = tid >> 5, lane = tid & 31;
    int wm = wid & 3, wn = wid >> 2;
    int grp = lane >> 2, qid = lane & 3;

    uint32_t dynB = smem_u32(dynsm);
    int arow = wm * 32 + (lane & 15);
    int acol = (lane >> 4) * 8;
    int brow = wn * 32 + ((lane >> 4) & 1) * 8 + (lane & 7);
    int bcol = ((lane >> 3) & 1) * 8;

    auto stage = [&](int buf, int k0) {
        uint32_t db = dynB + buf * UG_BUF;
#pragma unroll
        for (int i = 0; i < 2; i++) {
            int u = tid + i * 256;
            int r = u >> 2, sg = u & 3;
            size_t src = (size_t)toks[r] * HDIM + k0 + sg * 8;
            uint32_t so = db + (uint32_t)((r * S + sg * 8) * 2);
            CP_ASYNC16(so,         g_xhi + src);
            CP_ASYNC16(so + 10240, g_xlo + src);
        }
        {
            int r = tid >> 2, sg = tid & 3;
            size_t wo = (size_t)r * HDIM + k0 + sg * 8;
            uint32_t so = db + 20480 + (uint32_t)((r * S + sg * 8) * 2);
            CP_ASYNC16(so,        WU + wo);
            CP_ASYNC16(so + 5120, WG + wo);
        }
    };

    float accU[2][4][4], accG[2][4][4];
#pragma unroll
    for (int a = 0; a < 2; a++)
#pragma unroll
        for (int b = 0; b < 4; b++)
#pragma unroll
            for (int c = 0; c < 4; c++) { accU[a][b][c] = 0.f; accG[a][b][c] = 0.f; }

    const int NIT = HDIM / 32;   // 32
    stage(0, 0);
    CP_COMMIT();

    for (int it = 0; it < NIT; it++) {
        if (it + 1 < NIT) {
            stage((it + 1) & 1, (it + 1) * 32);
            CP_COMMIT();
            CP_WAIT1();
        } else {
            CP_WAIT0();
        }
        __syncthreads();

        uint32_t db = dynB + (it & 1) * UG_BUF;
        uint32_t AhB = db, AlB = db + 10240;
        uint32_t UB = db + 20480, GB = db + 25600;

#pragma unroll
        for (int ks = 0; ks < 2; ks++) {
            uint32_t ah[2][4], al[2][4];
#pragma unroll
            for (int mf = 0; mf < 2; mf++) {
                uint32_t ao = (uint32_t)(((arow + mf * 16) * S + ks * 16 + acol) * 2);
                LDMX4(ah[mf], AhB + ao);
                LDMX4(al[mf], AlB + ao);
            }
            uint32_t uh[8], gh[8];
#pragma unroll
            for (int p = 0; p < 2; p++) {
                uint32_t bo = (uint32_t)(((brow + p * 16) * S + ks * 16 + bcol) * 2);
                LDMX4(uh + p * 4, UB + bo);
                LDMX4(gh + p * 4, GB + bo);
            }
#pragma unroll
            for (int nf = 0; nf < 4; nf++) {
                uint32_t u0 = uh[nf * 2], u1 = uh[nf * 2 + 1];
                uint32_t g0 = gh[nf * 2], g1 = gh[nf * 2 + 1];
#pragma unroll
                for (int mf = 0; mf < 2; mf++) {
                    MMA_F16(accU[mf][nf], ah[mf], u0, u1);
                    MMA_F16(accU[mf][nf], al[mf], u0, u1);
                    MMA_F16(accG[mf][nf], ah[mf], g0, g1);
                    MMA_F16(accG[mf][nf], al[mf], g0, g1);
                }
            }
        }
        __syncthreads();
    }

    // epilogue: phi = silu(v)*u, split to fp16 hi/lo
#pragma unroll
    for (int mf = 0; mf < 2; mf++) {
#pragma unroll
        for (int half = 0; half < 2; half++) {
            int mloc = wm * 32 + mf * 16 + grp + half * 8;
            if (mloc >= valid) continue;
            size_t row = (size_t)(base + mloc);
#pragma unroll
            for (int nf = 0; nf < 4; nf++) {
                int fc = f0 + wn * 32 + nf * 8 + qid * 2;
                float u0 = accU[mf][nf][half * 2 + 0] + __ldg(b_up + e * FDIM + fc);
                float u1 = accU[mf][nf][half * 2 + 1] + __ldg(b_up + e * FDIM + fc + 1);
                float v0 = accG[mf][nf][half * 2 + 0] + __ldg(b_gate + e * FDIM + fc);
                float v1 = accG[mf][nf][half * 2 + 1] + __ldg(b_gate + e * FDIM + fc + 1);
                float p0 = (v0 / (1.f + __expf(-v0))) * u0;
                float p1 = (v1 / (1.f + __expf(-v1))) * u1;
                uint32_t lo;
                uint32_t hi = pack_hi_lo(p0, p1, lo);
                *reinterpret_cast<uint32_t*>(g_phi_hi + row * FDIM + fc) = hi;
                *reinterpret_cast<uint32_t*>(g_phi_lo + row * FDIM + fc) = lo;
            }
        }
    }
}

// ================= 7) down mma.sync GEMM + combine (fp16 2-term) ======
// block: 128 rows x 128 h, BK=32. 8 warps: 2 (m) x 4 (n). warp tile 64x32.
#define DN_BUF 30720    // Ah Al Bh (10240 ea)
#define DN_DSM (2 * DN_BUF)

__global__ __launch_bounds__(256) void down_mma(
    const float* __restrict__ b_down, float* __restrict__ out) {
    extern __shared__ char dynsm[];
    __shared__ int   toks[128];
    __shared__ float rws[128];

    int e = blockIdx.y >> 5;
    int t = blockIdx.y & 31;
    int cnt = g_cnt[e];
    int m0 = t * 128;
    if (m0 >= cnt) return;
    int base = g_off[e] + m0;
    int valid = min(128, cnt - m0);
    int h0 = blockIdx.x * 128;

    int tid = threadIdx.x;
    if (tid < 128) {
        int r = base + min(tid, valid - 1);
        toks[tid] = g_row_tok[r];
        rws[tid]  = g_row_w[r];
    }
    __syncthreads();

    const __half* WD = g_wdt + ((size_t)e * HDIM + h0) * FDIM;

    int wid = tid >> 5, lane = tid & 31;
    int wm = wid & 1, wn = wid >> 1;
    int grp = lane >> 2, qid = lane & 3;

    uint32_t dynB = smem_u32(dynsm);
    int arow = wm * 64 + (lane & 15);
    int acol = (lane >> 4) * 8;
    int brow = wn * 32 + ((lane >> 4) & 1) * 8 + (lane & 7);
    int bcol = ((lane >> 3) & 1) * 8;

    auto stage = [&](int buf, int k0) {
        uint32_t db = dynB + buf * DN_BUF;
#pragma unroll
        for (int i = 0; i < 2; i++) {
            int u = tid + i * 256;
            int r = u >> 2, sg = u & 3;
            size_t src = (size_t)(base + min(r, valid - 1)) * FDIM + k0 + sg * 8;
            uint32_t so = db + (uint32_t)((r * S + sg * 8) * 2);
            CP_ASYNC16(so,         g_phi_hi + src);
            CP_ASYNC16(so + 10240, g_phi_lo + src);
            size_t wo = (size_t)r * FDIM + k0 + sg * 8;
            CP_ASYNC16(so + 20480, WD + wo);
        }
    };

    float acc[4][4][4];
#pragma unroll
    for (int a = 0; a < 4; a++)
#pragma unroll
        for (int b = 0; b < 4; b++)
#pragma unroll
            for (int c = 0; c < 4; c++) acc[a][b][c] = 0.f;

    const int NIT = FDIM / 32;   // 64
    stage(0, 0);
    CP_COMMIT();

    for (int it = 0; it < NIT; it++) {
        if (it + 1 < NIT) {
            stage((it + 1) & 1, (it + 1) * 32);
            CP_COMMIT();
            CP_WAIT1();
        } else {
            CP_WAIT0();
        }
        __syncthreads();

        uint32_t db = dynB + (it & 1) * DN_BUF;
        uint32_t AhB = db, AlB = db + 10240, BB = db + 20480;

#pragma unroll
        for (int ks = 0; ks < 2; ks++) {
            uint32_t ah[4][4], al[4][4];
#pragma unroll
            for (int mf = 0; mf < 4; mf++) {
                uint32_t ao = (uint32_t)(((arow + mf * 16) * S + ks * 16 + acol) * 2);
                LDMX4(ah[mf], AhB + ao);
                LDMX4(al[mf], AlB + ao);
            }
            uint32_t bh[8];
#pragma unroll
            for (int p = 0; p < 2; p++) {
                uint32_t bo = (uint32_t)(((brow + p * 16) * S + ks * 16 + bcol) * 2);
                LDMX4(bh + p * 4, BB + bo);
            }
#pragma unroll
            for (int nf = 0; nf < 4; nf++) {
                uint32_t b0 = bh[nf * 2], b1 = bh[nf * 2 + 1];
#pragma unroll
                for (int mf = 0; mf < 4; mf++) {
                    MMA_F16(acc[mf][nf], ah[mf], b0, b1);
                    MMA_F16(acc[mf][nf], al[mf], b0, b1);
                }
            }
        }
        __syncthreads();
    }

    // epilogue: out[token] += w * (acc + b_down)
#pragma unroll
    for (int mf = 0; mf < 4; mf++) {
#pragma unroll
        for (int half = 0; half < 2; half++) {
            int mloc = wm * 64 + mf * 16 + grp + half * 8;
            if (mloc >= valid) continue;
            int token = toks[mloc];
            float w = rws[mloc];
            float* orow = out + (size_t)token * HDIM;
#pragma unroll
            for (int nf = 0; nf < 4; nf++) {
                int hc = h0 + wn * 32 + nf * 8 + qid * 2;
                float y0 = acc[mf][nf][half * 2 + 0] + __ldg(b_down + e * HDIM + hc);
                float y1 = acc[mf][nf][half * 2 + 1] + __ldg(b_down + e * HDIM + hc + 1);
                atomicAdd(orow + hc,     w * y0);
                atomicAdd(orow + hc + 1, w * y1);
            }
        }
    }
}

// ================= launch =================
extern "C" void kernel_launch(void* const* d_in, const int* in_sizes, int n_in,
                              void* d_out, int out_size) {
    const float* x      = (const float*)d_in[0];
    const float* gate_w = (const float*)d_in[1];
    const float* w_up   = (const float*)d_in[2];
    const float* w_gate = (const float*)d_in[3];
    const float* w_down = (const float*)d_in[4];
    const float* b_up   = (const float*)d_in[5];
    const float* b_gate = (const float*)d_in[6];
    const float* b_down = (const float*)d_in[7];

    float* out = (float*)d_out;
    float* rl  = out + (size_t)NTOK * HDIM;

    cudaFuncSetAttribute(up_gate_mma,
                         cudaFuncAttributeMaxDynamicSharedMemorySize, UG_DSM);
    cudaFuncSetAttribute(down_mma,
                         cudaFuncAttributeMaxDynamicSharedMemorySize, DN_DSM);

    init_kernel<<<1024, 256>>>(out);
    router_kernel<<<NTOK / 4, 128>>>(x, gate_w, rl);
    scan_kernel<<<1, 32>>>();
    scatter_kernel<<<NTOK / 256, 256>>>();

    split_x_kernel<<<(NTOK * HDIM / 4) / 256, 256>>>(x);
    {
        dim3 thr(32, 8);
        dim3 g1(FDIM / 32, HDIM / 64, EXPE);
        transpose_cvt_kernel<<<g1, thr>>>(w_up,   0, HDIM, FDIM);
        transpose_cvt_kernel<<<g1, thr>>>(w_gate, 1, HDIM, FDIM);
        dim3 g2(HDIM / 32, FDIM / 64, EXPE);
        transpose_cvt_kernel<<<g2, thr>>>(w_down, 2, FDIM, HDIM);
    }

    dim3 gridA(FDIM / 64, EXPE * 32);
    up_gate_mma<<<gridA, 256, UG_DSM>>>(b_up, b_gate);

    dim3 gridB(HDIM / 128, EXPE * 32);
    down_mma<<<gridB, 256, DN_DSM>>>(b_down, out);
}

// round 13
// speedup vs baseline: 5.7267x; 1.4544x over previous
#include <cuda_runtime.h>
#include <cuda_fp16.h>
#include <cstdint>

#define NTOK 4096
#define HDIM 1024
#define FDIM 2048
#define EXPE 8
#define NPAIR (NTOK * 2)

// ================= scratch (static device globals) =================
__device__ __half g_xh[(size_t)NTOK * HDIM];
// transposed weights (single fp16): K (=H or F) contiguous
__device__ __half g_wut[(size_t)EXPE * FDIM * HDIM]; // [E][F][H]
__device__ __half g_wgt[(size_t)EXPE * FDIM * HDIM];
__device__ __half g_wdt[(size_t)EXPE * HDIM * FDIM]; // [E][H][F]
__device__ __half g_phi[(size_t)NPAIR * FDIM];
__device__ int   g_cnt[EXPE];
__device__ int   g_off[EXPE + 1];
__device__ int   g_cur[EXPE];
__device__ int   g_tok_e[NTOK * 2];
__device__ float g_tok_w[NTOK * 2];
__device__ int   g_row_tok[NPAIR];
__device__ float g_row_w[NPAIR];

__device__ __forceinline__ uint32_t smem_u32(const void* p) {
    uint32_t a;
    asm("{ .reg .u64 t; cvta.to.shared.u64 t, %1; cvt.u32.u64 %0, t; }"
        : "=r"(a) : "l"(p));
    return a;
}

// mma.sync fp16 in / fp32 acc (sm_80+ baseline PTX)
#define MMA_F16(acc, a, b0, b1)                                                 \
    asm volatile(                                                               \
        "mma.sync.aligned.m16n8k16.row.col.f32.f16.f16.f32 "                    \
        "{%0,%1,%2,%3}, {%4,%5,%6,%7}, {%8,%9}, {%0,%1,%2,%3};"                 \
        : "+f"((acc)[0]), "+f"((acc)[1]), "+f"((acc)[2]), "+f"((acc)[3])        \
        : "r"((a)[0]), "r"((a)[1]), "r"((a)[2]), "r"((a)[3]), "r"(b0), "r"(b1))

#define LDMX4(r, addr)                                                          \
    asm volatile("ldmatrix.sync.aligned.m8n8.x4.shared.b16 {%0,%1,%2,%3}, [%4];"\
        : "=r"((r)[0]), "=r"((r)[1]), "=r"((r)[2]), "=r"((r)[3]) : "r"(addr))

#define CP_ASYNC16(sm, gp)                                                      \
    asm volatile("cp.async.cg.shared.global [%0], [%1], 16;"                    \
                 :: "r"(sm), "l"(gp))
#define CP_COMMIT() asm volatile("cp.async.commit_group;" ::: "memory")
#define CP_WAIT1()  asm volatile("cp.async.wait_group 1;" ::: "memory")
#define CP_WAIT0()  asm volatile("cp.async.wait_group 0;" ::: "memory")

__device__ __forceinline__ uint32_t pack2(float a, float b) {
    __half2 h = __floats2half2_rn(a, b);
    return *reinterpret_cast<uint32_t*>(&h);
}

// ================= 0) init =================
__global__ void init_kernel(float* __restrict__ out) {
    int tid = blockIdx.x * blockDim.x + threadIdx.x;
    if (tid < EXPE) g_cnt[tid] = 0;
    const int total = NTOK * HDIM;
    for (int i = tid * 4; i < total; i += gridDim.x * blockDim.x * 4)
        *reinterpret_cast<float4*>(out + i) = make_float4(0.f, 0.f, 0.f, 0.f);
}

// ================= 1) router =================
__global__ void router_kernel(const float* __restrict__ x,
                              const float* __restrict__ gw,
                              float* __restrict__ rl_out) {
    __shared__ float sgw[EXPE * HDIM];
    int tid = threadIdx.x;
    for (int i = tid; i < EXPE * HDIM; i += 128) sgw[i] = gw[i];
    __syncthreads();

    int warp = tid >> 5, lane = tid & 31;
    int n = blockIdx.x * 4 + warp;
    if (n >= NTOK) return;
    const float* xr = x + (size_t)n * HDIM;

    float acc[EXPE];
#pragma unroll
    for (int e = 0; e < EXPE; e++) acc[e] = 0.f;
    for (int h = lane; h < HDIM; h += 32) {
        float xv = xr[h];
#pragma unroll
        for (int e = 0; e < EXPE; e++) acc[e] += xv * sgw[e * HDIM + h];
    }
#pragma unroll
    for (int e = 0; e < EXPE; e++)
#pragma unroll
        for (int o = 16; o > 0; o >>= 1)
            acc[e] += __shfl_xor_sync(0xffffffffu, acc[e], o);

    if (lane == 0) {
#pragma unroll
        for (int e = 0; e < EXPE; e++) rl_out[(size_t)n * EXPE + e] = acc[e];
        float m = acc[0];
#pragma unroll
        for (int e = 1; e < EXPE; e++) m = fmaxf(m, acc[e]);
        float p[EXPE];
#pragma unroll
        for (int e = 0; e < EXPE; e++) p[e] = __expf(acc[e] - m);
        int i0 = 0;
#pragma unroll
        for (int e = 1; e < EXPE; e++) if (p[e] > p[i0]) i0 = e;
        int i1 = (i0 == 0) ? 1 : 0;
#pragma unroll
        for (int e = 0; e < EXPE; e++)
            if (e != i0 && p[e] > p[i1]) i1 = e;
        float s2 = p[i0] + p[i1];
        g_tok_e[n * 2 + 0] = i0; g_tok_w[n * 2 + 0] = p[i0] / s2;
        g_tok_e[n * 2 + 1] = i1; g_tok_w[n * 2 + 1] = p[i1] / s2;
        atomicAdd(&g_cnt[i0], 1);
        atomicAdd(&g_cnt[i1], 1);
    }
}

// ================= 2) scan =================
__global__ void scan_kernel() {
    if (threadIdx.x == 0 && blockIdx.x == 0) {
        int acc = 0;
        for (int e = 0; e < EXPE; e++) {
            g_off[e] = acc; g_cur[e] = acc; acc += g_cnt[e];
        }
        g_off[EXPE] = acc;
    }
}

// ================= 3) scatter =================
__global__ void scatter_kernel() {
    int n = blockIdx.x * blockDim.x + threadIdx.x;
    if (n >= NTOK) return;
#pragma unroll
    for (int k = 0; k < 2; k++) {
        int e = g_tok_e[n * 2 + k];
        int pos = atomicAdd(&g_cur[e], 1);
        g_row_tok[pos] = n;
        g_row_w[pos] = g_tok_w[n * 2 + k];
    }
}

// ================= 4) convert x to fp16 =================
__global__ void cvt_x_kernel(const float* __restrict__ x) {
    int i = blockIdx.x * blockDim.x + threadIdx.x;
    float4 v = reinterpret_cast<const float4*>(x)[i];
    uint2 o;
    o.x = pack2(v.x, v.y);
    o.y = pack2(v.z, v.w);
    reinterpret_cast<uint2*>(g_xh)[i] = o;
}

// ================= 5) transpose + fp16-convert weights =================
// Destinations bound in device code (round-8 ATS lesson).
__global__ void transpose_cvt_kernel(const float* __restrict__ src,
                                     int which, int R, int C) {
    __half* dst;
    if (which == 0)      dst = g_wut;
    else if (which == 1) dst = g_wgt;
    else                 dst = g_wdt;

    __shared__ float t[64][33];
    int e = blockIdx.z;
    const float* s = src + (size_t)e * R * C;
    int c0 = blockIdx.x * 32, r0 = blockIdx.y * 64;
    int tx = threadIdx.x, ty = threadIdx.y;
#pragma unroll
    for (int i = ty; i < 64; i += 8)
        t[i][tx] = s[(size_t)(r0 + i) * C + c0 + tx];
    __syncthreads();
#pragma unroll
    for (int j = ty; j < 32; j += 8) {
        uint32_t hp = pack2(t[2 * tx][j], t[2 * tx + 1][j]);
        size_t o = ((size_t)e * C + c0 + j) * R + r0 + 2 * tx;
        *reinterpret_cast<uint32_t*>(dst + o) = hp;
    }
}

// ================= 6) up+gate mma.sync GEMM (plain fp16) ==============
// block: 128 rows x 64 f, BK=32. 8 warps: 4 (m) x 2 (n). warp tile 32x32.
#define S 40            // padded smem stride (elements)
#define UG_BUF 20480    // A (10240) + Bu Bg (5120 ea)
#define UG_DSM (2 * UG_BUF)

__global__ __launch_bounds__(256) void up_gate_mma(
    const float* __restrict__ b_up, const float* __restrict__ b_gate) {
    extern __shared__ char dynsm[];
    __shared__ int toks[128];

    int e = blockIdx.y >> 5;
    int t = blockIdx.y & 31;
    int cnt = g_cnt[e];
    int m0 = t * 128;
    if (m0 >= cnt) return;
    int base = g_off[e] + m0;
    int valid = min(128, cnt - m0);
    int f0 = blockIdx.x * 64;

    int tid = threadIdx.x;
    if (tid < 128) toks[tid] = g_row_tok[base + min(tid, valid - 1)];
    __syncthreads();

    const __half* WU = g_wut + ((size_t)e * FDIM + f0) * HDIM;
    const __half* WG = g_wgt + ((size_t)e * FDIM + f0) * HDIM;

    int wid = tid >> 5, lane = tid & 31;
    int wm = wid & 3, wn = wid >> 2;
    int grp = lane >> 2, qid = lane & 3;

    uint32_t dynB = smem_u32(dynsm);
    int arow = wm * 32 + (lane & 15);
    int acol = (lane >> 4) * 8;
    int brow = wn * 32 + ((lane >> 4) & 1) * 8 + (lane & 7);
    int bcol = ((lane >> 3) & 1) * 8;

    auto stage = [&](int buf, int k0) {
        uint32_t db = dynB + buf * UG_BUF;
        // A: 128 rows x 32 k = 512 16B segs over 2 iters
#pragma unroll
        for (int i = 0; i < 2; i++) {
            int u = tid + i * 256;
            int r = u >> 2, sg = u & 3;
            size_t src = (size_t)toks[r] * HDIM + k0 + sg * 8;
            uint32_t so = db + (uint32_t)((r * S + sg * 8) * 2);
            CP_ASYNC16(so, g_xh + src);
        }
        // B: 64 rows x 32 k, 2 matrices
        {
            int r = tid >> 2, sg = tid & 3;
            size_t wo = (size_t)r * HDIM + k0 + sg * 8;
            uint32_t so = db + 10240 + (uint32_t)((r * S + sg * 8) * 2);
            CP_ASYNC16(so,        WU + wo);
            CP_ASYNC16(so + 5120, WG + wo);
        }
    };

    float accU[2][4][4], accG[2][4][4];
#pragma unroll
    for (int a = 0; a < 2; a++)
#pragma unroll
        for (int b = 0; b < 4; b++)
#pragma unroll
            for (int c = 0; c < 4; c++) { accU[a][b][c] = 0.f; accG[a][b][c] = 0.f; }

    const int NIT = HDIM / 32;   // 32
    stage(0, 0);
    CP_COMMIT();

    for (int it = 0; it < NIT; it++) {
        if (it + 1 < NIT) {
            stage((it + 1) & 1, (it + 1) * 32);
            CP_COMMIT();
            CP_WAIT1();
        } else {
            CP_WAIT0();
        }
        __syncthreads();

        uint32_t db = dynB + (it & 1) * UG_BUF;
        uint32_t AB = db, UB = db + 10240, GB = db + 15360;

#pragma unroll
        for (int ks = 0; ks < 2; ks++) {
            uint32_t ah[2][4];
#pragma unroll
            for (int mf = 0; mf < 2; mf++) {
                uint32_t ao = (uint32_t)(((arow + mf * 16) * S + ks * 16 + acol) * 2);
                LDMX4(ah[mf], AB + ao);
            }
            uint32_t uh[8], gh[8];
#pragma unroll
            for (int p = 0; p < 2; p++) {
                uint32_t bo = (uint32_t)(((brow + p * 16) * S + ks * 16 + bcol) * 2);
                LDMX4(uh + p * 4, UB + bo);
                LDMX4(gh + p * 4, GB + bo);
            }
#pragma unroll
            for (int nf = 0; nf < 4; nf++) {
                uint32_t u0 = uh[nf * 2], u1 = uh[nf * 2 + 1];
                uint32_t g0 = gh[nf * 2], g1 = gh[nf * 2 + 1];
#pragma unroll
                for (int mf = 0; mf < 2; mf++) {
                    MMA_F16(accU[mf][nf], ah[mf], u0, u1);
                    MMA_F16(accG[mf][nf], ah[mf], g0, g1);
                }
            }
        }
        __syncthreads();
    }

    // epilogue: phi = silu(v)*u, single fp16
#pragma unroll
    for (int mf = 0; mf < 2; mf++) {
#pragma unroll
        for (int half = 0; half < 2; half++) {
            int mloc = wm * 32 + mf * 16 + grp + half * 8;
            if (mloc >= valid) continue;
            size_t row = (size_t)(base + mloc);
#pragma unroll
            for (int nf = 0; nf < 4; nf++) {
                int fc = f0 + wn * 32 + nf * 8 + qid * 2;
                float u0 = accU[mf][nf][half * 2 + 0] + __ldg(b_up + e * FDIM + fc);
                float u1 = accU[mf][nf][half * 2 + 1] + __ldg(b_up + e * FDIM + fc + 1);
                float v0 = accG[mf][nf][half * 2 + 0] + __ldg(b_gate + e * FDIM + fc);
                float v1 = accG[mf][nf][half * 2 + 1] + __ldg(b_gate + e * FDIM + fc + 1);
                float p0 = (v0 / (1.f + __expf(-v0))) * u0;
                float p1 = (v1 / (1.f + __expf(-v1))) * u1;
                *reinterpret_cast<uint32_t*>(g_phi + row * FDIM + fc) = pack2(p0, p1);
            }
        }
    }
}

// ================= 7) down mma.sync GEMM + combine (plain fp16) =======
// block: 128 rows x 128 h, BK=32. 8 warps: 2 (m) x 4 (n). warp tile 64x32.
#define DN_BUF 20480    // A (10240) + B (10240)
#define DN_DSM (2 * DN_BUF)

__global__ __launch_bounds__(256) void down_mma(
    const float* __restrict__ b_down, float* __restrict__ out) {
    extern __shared__ char dynsm[];
    __shared__ int   toks[128];
    __shared__ float rws[128];

    int e = blockIdx.y >> 5;
    int t = blockIdx.y & 31;
    int cnt = g_cnt[e];
    int m0 = t * 128;
    if (m0 >= cnt) return;
    int base = g_off[e] + m0;
    int valid = min(128, cnt - m0);
    int h0 = blockIdx.x * 128;

    int tid = threadIdx.x;
    if (tid < 128) {
        int r = base + min(tid, valid - 1);
        toks[tid] = g_row_tok[r];
        rws[tid]  = g_row_w[r];
    }
    __syncthreads();

    const __half* WD = g_wdt + ((size_t)e * HDIM + h0) * FDIM;

    int wid = tid >> 5, lane = tid & 31;
    int wm = wid & 1, wn = wid >> 1;
    int grp = lane >> 2, qid = lane & 3;

    uint32_t dynB = smem_u32(dynsm);
    int arow = wm * 64 + (lane & 15);
    int acol = (lane >> 4) * 8;
    int brow = wn * 32 + ((lane >> 4) & 1) * 8 + (lane & 7);
    int bcol = ((lane >> 3) & 1) * 8;

    auto stage = [&](int buf, int k0) {
        uint32_t db = dynB + buf * DN_BUF;
#pragma unroll
        for (int i = 0; i < 2; i++) {
            int u = tid + i * 256;
            int r = u >> 2, sg = u & 3;
            size_t src = (size_t)(base + min(r, valid - 1)) * FDIM + k0 + sg * 8;
            uint32_t so = db + (uint32_t)((r * S + sg * 8) * 2);
            CP_ASYNC16(so, g_phi + src);
            size_t wo = (size_t)r * FDIM + k0 + sg * 8;
            CP_ASYNC16(so + 10240, WD + wo);
        }
    };

    float acc[4][4][4];
#pragma unroll
    for (int a = 0; a < 4; a++)
#pragma unroll
        for (int b = 0; b < 4; b++)
#pragma unroll
            for (int c = 0; c < 4; c++) acc[a][b][c] = 0.f;

    const int NIT = FDIM / 32;   // 64
    stage(0, 0);
    CP_COMMIT();

    for (int it = 0; it < NIT; it++) {
        if (it + 1 < NIT) {
            stage((it + 1) & 1, (it + 1) * 32);
            CP_COMMIT();
            CP_WAIT1();
        } else {
            CP_WAIT0();
        }
        __syncthreads();

        uint32_t db = dynB + (it & 1) * DN_BUF;
        uint32_t AB = db, BB = db + 10240;

#pragma unroll
        for (int ks = 0; ks < 2; ks++) {
            uint32_t ah[4][4];
#pragma unroll
            for (int mf = 0; mf < 4; mf++) {
                uint32_t ao = (uint32_t)(((arow + mf * 16) * S + ks * 16 + acol) * 2);
                LDMX4(ah[mf], AB + ao);
            }
            uint32_t bh[8];
#pragma unroll
            for (int p = 0; p < 2; p++) {
                uint32_t bo = (uint32_t)(((brow + p * 16) * S + ks * 16 + bcol) * 2);
                LDMX4(bh + p * 4, BB + bo);
            }
#pragma unroll
            for (int nf = 0; nf < 4; nf++) {
                uint32_t b0 = bh[nf * 2], b1 = bh[nf * 2 + 1];
#pragma unroll
                for (int mf = 0; mf < 4; mf++)
                    MMA_F16(acc[mf][nf], ah[mf], b0, b1);
            }
        }
        __syncthreads();
    }

    // epilogue: out[token] += w * (acc + b_down)
#pragma unroll
    for (int mf = 0; mf < 4; mf++) {
#pragma unroll
        for (int half = 0; half < 2; half++) {
            int mloc = wm * 64 + mf * 16 + grp + half * 8;
            if (mloc >= valid) continue;
            int token = toks[mloc];
            float w = rws[mloc];
            float* orow = out + (size_t)token * HDIM;
#pragma unroll
            for (int nf = 0; nf < 4; nf++) {
                int hc = h0 + wn * 32 + nf * 8 + qid * 2;
                float y0 = acc[mf][nf][half * 2 + 0] + __ldg(b_down + e * HDIM + hc);
                float y1 = acc[mf][nf][half * 2 + 1] + __ldg(b_down + e * HDIM + hc + 1);
                atomicAdd(orow + hc,     w * y0);
                atomicAdd(orow + hc + 1, w * y1);
            }
        }
    }
}

// ================= launch =================
extern "C" void kernel_launch(void* const* d_in, const int* in_sizes, int n_in,
                              void* d_out, int out_size) {
    const float* x      = (const float*)d_in[0];
    const float* gate_w = (const float*)d_in[1];
    const float* w_up   = (const float*)d_in[2];
    const float* w_gate = (const float*)d_in[3];
    const float* w_down = (const float*)d_in[4];
    const float* b_up   = (const float*)d_in[5];
    const float* b_gate = (const float*)d_in[6];
    const float* b_down = (const float*)d_in[7];

    float* out = (float*)d_out;
    float* rl  = out + (size_t)NTOK * HDIM;

    cudaFuncSetAttribute(up_gate_mma,
                         cudaFuncAttributeMaxDynamicSharedMemorySize, UG_DSM);
    cudaFuncSetAttribute(down_mma,
                         cudaFuncAttributeMaxDynamicSharedMemorySize, DN_DSM);

    init_kernel<<<1024, 256>>>(out);
    router_kernel<<<NTOK / 4, 128>>>(x, gate_w, rl);
    scan_kernel<<<1, 32>>>();
    scatter_kernel<<<NTOK / 256, 256>>>();

    cvt_x_kernel<<<(NTOK * HDIM / 4) / 256, 256>>>(x);
    {
        dim3 thr(32, 8);
        dim3 g1(FDIM / 32, HDIM / 64, EXPE);
        transpose_cvt_kernel<<<g1, thr>>>(w_up,   0, HDIM, FDIM);
        transpose_cvt_kernel<<<g1, thr>>>(w_gate, 1, HDIM, FDIM);
        dim3 g2(HDIM / 32, FDIM / 64, EXPE);
        transpose_cvt_kernel<<<g2, thr>>>(w_down, 2, FDIM, HDIM);
    }

    dim3 gridA(FDIM / 64, EXPE * 32);
    up_gate_mma<<<gridA, 256, UG_DSM>>>(b_up, b_gate);

    dim3 gridB(HDIM / 128, EXPE * 32);
    down_mma<<<gridB, 256, DN_DSM>>>(b_down, out);
}